// round 8
// baseline (speedup 1.0000x reference)
#include <cuda_runtime.h>
#include <math.h>
#include <stdint.h>

#define NB   4
#define HW   4096
#define DH   128
#define NTOK 4096

// Scratch (device globals; allocation-free).
// Q: A-frag m16n8k32 [b][mt(256)][ks(4)][lane(32)][4 u32]
// K: paired B-frag   [b][tile(64)][ntp(4)][ks(4)][lane(32)][4 u32] (8 KB/tile)
// V: paired B-frag   [b][tile(64)][dtp(8)][u(2)][lane(32)][4 u32]  (8 KB/tile)
//    key order pi-permuted so P C-frags pack directly into fp8 A-frags.
// O partials: [z(2)][b][n][d] fp32 unnormalized;  L partials: [z(2)][b][n].
__device__ uint32_t g_Q[NB * 131072];
__device__ uint32_t g_K[NB * 131072];
__device__ uint32_t g_V[NB * 131072];
__device__ float    g_O[2 * NB * NTOK * DH];
__device__ float    g_L[2 * NB * NTOK];

// log2(e)/sqrt(128): Q pre-scale so softmax runs in exp2 domain.
#define QSCALE (0.08838834764831845f * 1.4426950408889634f)

__device__ __forceinline__ float ex2f(float x) {
    float y; asm("ex2.approx.f32 %0, %1;" : "=f"(y) : "f"(x)); return y;
}
__device__ __forceinline__ uint32_t pack4_e4m3(float f0, float f1, float f2, float f3) {
    uint32_t r;
    asm("{\n\t.reg .b16 lo, hi;\n\t"
        "cvt.rn.satfinite.e4m3x2.f32 lo, %2, %1;\n\t"
        "cvt.rn.satfinite.e4m3x2.f32 hi, %4, %3;\n\t"
        "mov.b32 %0, {lo, hi};\n\t}"
        : "=r"(r) : "f"(f0), "f"(f1), "f"(f2), "f"(f3));
    return r;
}
__device__ __forceinline__ uint32_t e4m3_byte(float x) {
    uint16_t h;
    asm("{\n\t.reg .b16 t;\n\tcvt.rn.satfinite.e4m3x2.f32 t, %1, %1;\n\tmov.b16 %0, t;\n\t}"
        : "=h"(h) : "f"(x));
    return (uint32_t)(h & 0xFF);
}
__device__ __forceinline__ void mma_e4m3(float* d,
    uint32_t a0, uint32_t a1, uint32_t a2, uint32_t a3, uint32_t b0, uint32_t b1)
{
    asm volatile(
        "mma.sync.aligned.m16n8k32.row.col.f32.e4m3.e4m3.f32 "
        "{%0,%1,%2,%3},{%4,%5,%6,%7},{%8,%9},{%0,%1,%2,%3};"
        : "+f"(d[0]), "+f"(d[1]), "+f"(d[2]), "+f"(d[3])
        : "r"(a0), "r"(a1), "r"(a2), "r"(a3), "r"(b0), "r"(b1));
}
__device__ __forceinline__ void mma_e4m3_init(float* d,
    uint32_t a0, uint32_t a1, uint32_t a2, uint32_t a3, uint32_t b0, uint32_t b1)
{
    asm volatile(
        "mma.sync.aligned.m16n8k32.row.col.f32.e4m3.e4m3.f32 "
        "{%0,%1,%2,%3},{%4,%5,%6,%7},{%8,%9},{%10,%11,%12,%13};"
        : "=f"(d[0]), "=f"(d[1]), "=f"(d[2]), "=f"(d[3])
        : "r"(a0), "r"(a1), "r"(a2), "r"(a3), "r"(b0), "r"(b1),
          "f"(0.f), "f"(0.f), "f"(0.f), "f"(0.f));
}
__device__ __forceinline__ void cp_async16(void* smem_dst, const void* gmem_src) {
    uint32_t s = (uint32_t)__cvta_generic_to_shared(smem_dst);
    asm volatile("cp.async.cg.shared.global [%0], [%1], 16;\n" :: "r"(s), "l"(gmem_src));
}
#define CP_COMMIT() asm volatile("cp.async.commit_group;\n" ::: "memory")
template<int N> __device__ __forceinline__ void cp_wait() {
    asm volatile("cp.async.wait_group %0;\n" :: "n"(N) : "memory");
}

// ---------------------------------------------------------------------------
// Merged Q/K/V 1x1-conv projection (same as round 7, proven correct).
// ---------------------------------------------------------------------------
__global__ __launch_bounds__(256) void proj_qkv(
    const float* __restrict__ xu, const float* __restrict__ xl,
    const float* __restrict__ wq, const float* __restrict__ bq,
    const float* __restrict__ wk, const float* __restrict__ bk,
    const float* __restrict__ wv, const float* __restrict__ bv,
    uint32_t* __restrict__ Qo, uint32_t* __restrict__ Ko,
    uint32_t* __restrict__ Vo)
{
    __shared__ float xs[16][256];
    __shared__ float ws[32][16];

    const int m  = blockIdx.z % 3;
    const int b  = blockIdx.z / 3;
    const int CIN = (m == 0) ? 64 : 128;
    const float* x    = (m == 0) ? (xu + (size_t)b * 64 * HW)
                                 : (xl + (size_t)b * 128 * HW);
    const float* w    = (m == 0) ? wq : (m == 1) ? wk : wv;
    const float* bias = (m == 0) ? bq : (m == 1) ? bk : bv;

    const int c0 = blockIdx.y * 32, s0 = blockIdx.x * 256;
    const int tid = threadIdx.x, tx = tid & 63, ty = tid >> 6;

    float acc[8][4];
#pragma unroll
    for (int i = 0; i < 8; i++)
#pragma unroll
        for (int j = 0; j < 4; j++) acc[i][j] = 0.f;

    for (int k0 = 0; k0 < CIN; k0 += 16) {
        __syncthreads();
#pragma unroll
        for (int t = 0; t < 4; t++) {
            int f = tid + 256 * t, r = f >> 6, c4 = (f & 63) << 2;
            *(float4*)&xs[r][c4] = *(const float4*)(x + (size_t)(k0 + r) * HW + s0 + c4);
        }
#pragma unroll
        for (int t = 0; t < 2; t++) {
            int f = tid + 256 * t;
            ws[f >> 4][f & 15] = w[(size_t)(c0 + (f >> 4)) * CIN + k0 + (f & 15)];
        }
        __syncthreads();
#pragma unroll
        for (int k = 0; k < 16; k++) {
            float4 xv = *(float4*)&xs[k][tx << 2];
#pragma unroll
            for (int cc = 0; cc < 8; cc++) {
                float wv = ws[ty * 8 + cc][k];
                acc[cc][0] = fmaf(wv, xv.x, acc[cc][0]);
                acc[cc][1] = fmaf(wv, xv.y, acc[cc][1]);
                acc[cc][2] = fmaf(wv, xv.z, acc[cc][2]);
                acc[cc][3] = fmaf(wv, xv.w, acc[cc][3]);
            }
        }
    }

#pragma unroll
    for (int cc = 0; cc < 8; cc++) {
        const int c = c0 + ty * 8 + cc;
        const float bv_ = bias[c];
        const int s = s0 + (tx << 2);
        float v0 = acc[cc][0] + bv_, v1 = acc[cc][1] + bv_;
        float v2 = acc[cc][2] + bv_, v3 = acc[cc][3] + bv_;
        const int d0 = s & 127;
        const int n  = c * 32 + (s >> 7);
        const int ks = d0 >> 5, dd = d0 & 31;
        const int h = dd >> 4, t = (dd >> 2) & 3;

        if (m == 0) {
            int mt = n >> 4, r = n & 15;
            int g = r & 7, hi = r >> 3;
            size_t idx = (((size_t)b * 256 + mt) * 4 + ks) * 128
                       + (g * 4 + t) * 4 + hi + 2 * h;
            Qo[idx] = pack4_e4m3(v0 * QSCALE, v1 * QSCALE, v2 * QSCALE, v3 * QSCALE);
        } else if (m == 1) {
            int tile = n >> 6, j = n & 63;
            int nt = j >> 3, g = j & 7, ntp = nt >> 1, odd = nt & 1;
            size_t idx = (size_t)b * 131072 + (size_t)tile * 2048
                       + ((ntp * 4 + ks) * 32 + g * 4 + t) * 4 + odd * 2 + h;
            Ko[idx] = pack4_e4m3(v0, v1, v2, v3);
        } else {
            int tile = n >> 6, j = n & 63;
            int u  = j >> 5, jl = j & 31;
            int hv = jl >> 4, cpv = (jl >> 3) & 1, tv = (jl >> 1) & 3, c1 = jl & 1;
            int cv = cpv * 2 + c1;
            char* base = (char*)Vo + (size_t)b * 524288 + (size_t)tile * 8192;
            float vv[4] = {v0, v1, v2, v3};
#pragma unroll
            for (int q4 = 0; q4 < 4; q4++) {
                int d = d0 + q4;
                int dtp = d >> 4, odd = (d >> 3) & 1, g = d & 7;
                base[(((dtp * 2 + u) * 32 + g * 4 + tv) * 4 + odd * 2 + hv) * 4 + cv] =
                    (char)e4m3_byte(vv[q4]);
            }
        }
    }
}

// ---------------------------------------------------------------------------
// fp8 flash, KV-split: blockIdx.z picks key half (32 tiles). BM=64, 128 thr,
// __launch_bounds__(128,4) -> <=128 regs, ~3.5 CTAs/SM. Writes UNNORMALIZED
// o-partials + l-partials; merge happens in proj_out.
// S processed in two 32-key halves (sf = 16 regs, softmax fused per half).
// ---------------------------------------------------------------------------
__global__ __launch_bounds__(128, 4) void flash_kernel(
    const uint4* __restrict__ Qg, const char* __restrict__ Kg_,
    const char* __restrict__ Vg_, float* __restrict__ Op,
    float* __restrict__ Lp)
{
    extern __shared__ uint32_t sm[];   // 3 stages x (K 2048 u32 + V 2048 u32)

    const int b = blockIdx.y, bx = blockIdx.x, z = blockIdx.z;
    const int tid = threadIdx.x, w = tid >> 5, lane = tid & 31;
    const int g = lane >> 2, t = lane & 3;

    const char* Kg = Kg_ + (size_t)b * 524288 + (size_t)z * 32 * 8192;
    const char* Vg = Vg_ + (size_t)b * 524288 + (size_t)z * 32 * 8192;

    auto issueKV = [&](int i) {
        uint32_t st = (uint32_t)(i % 3) * 4096;
        const char* kg = Kg + (size_t)i * 8192;
        const char* vg = Vg + (size_t)i * 8192;
#pragma unroll
        for (int tt = 0; tt < 4; tt++) {
            int f = (tid + 128 * tt) * 16;
            cp_async16((char*)(sm + st) + f, kg + f);
        }
#pragma unroll
        for (int tt = 0; tt < 4; tt++) {
            int f = (tid + 128 * tt) * 16;
            cp_async16((char*)(sm + st + 2048) + f, vg + f);
        }
        CP_COMMIT();
    };
    issueKV(0); issueKV(1);

    // Q A-frags (4 k32 chunks) -> registers
    uint4 q[4];
    {
        const uint4* qp = Qg + ((size_t)(b * 256 + bx * 4 + w) * 4) * 32 + lane;
#pragma unroll
        for (int ks = 0; ks < 4; ks++) q[ks] = qp[ks * 32];
    }

    float o[16][4];
#pragma unroll
    for (int dt = 0; dt < 16; dt++)
#pragma unroll
        for (int j = 0; j < 4; j++) o[dt][j] = 0.f;
    float ls0 = 0.f, ls1 = 0.f;

    for (int i = 0; i < 32; i++) {
        cp_wait<1>();
        __syncthreads();
        if (i + 2 < 32) issueKV(i + 2); else CP_COMMIT();

        const uint32_t* ksb = sm + (uint32_t)(i % 3) * 4096;
        const uint32_t* vsb = ksb + 2048;

        uint32_t pa[2][4];
#pragma unroll
        for (int u = 0; u < 2; u++) {
            // ---- S half u: keys 32u..32u+31 (ntp 2u, 2u+1) ----
            float sf[4][4];
#pragma unroll
            for (int ks = 0; ks < 4; ks++) {
#pragma unroll
                for (int p = 0; p < 2; p++) {
                    const int ntp = 2 * u + p;
                    uint4 kb = *(const uint4*)(ksb + (ntp * 4 + ks) * 128 + lane * 4);
                    if (ks == 0) {
                        mma_e4m3_init(sf[p * 2],     q[ks].x, q[ks].y, q[ks].z, q[ks].w, kb.x, kb.y);
                        mma_e4m3_init(sf[p * 2 + 1], q[ks].x, q[ks].y, q[ks].z, q[ks].w, kb.z, kb.w);
                    } else {
                        mma_e4m3(sf[p * 2],     q[ks].x, q[ks].y, q[ks].z, q[ks].w, kb.x, kb.y);
                        mma_e4m3(sf[p * 2 + 1], q[ks].x, q[ks].y, q[ks].z, q[ks].w, kb.z, kb.w);
                    }
                }
            }
            // ---- softmax (no max, exp2) + fp8 P A-frag pack ----
            float e[4][4];
#pragma unroll
            for (int k = 0; k < 4; k++) {
                e[k][0] = ex2f(sf[k][0]); e[k][1] = ex2f(sf[k][1]);
                e[k][2] = ex2f(sf[k][2]); e[k][3] = ex2f(sf[k][3]);
                ls0 += e[k][0] + e[k][1];
                ls1 += e[k][2] + e[k][3];
            }
            pa[u][0] = pack4_e4m3(e[0][0], e[0][1], e[1][0], e[1][1]);
            pa[u][1] = pack4_e4m3(e[0][2], e[0][3], e[1][2], e[1][3]);
            pa[u][2] = pack4_e4m3(e[2][0], e[2][1], e[3][0], e[3][1]);
            pa[u][3] = pack4_e4m3(e[2][2], e[2][3], e[3][2], e[3][3]);
        }

        // ---- PV(i): o += P @ V (keys pi-permuted in V image) ----
#pragma unroll
        for (int u = 0; u < 2; u++) {
#pragma unroll
            for (int dtp = 0; dtp < 8; dtp++) {
                uint4 vv = *(const uint4*)(vsb + (dtp * 2 + u) * 128 + lane * 4);
                mma_e4m3(o[dtp * 2],     pa[u][0], pa[u][1], pa[u][2], pa[u][3], vv.x, vv.y);
                mma_e4m3(o[dtp * 2 + 1], pa[u][0], pa[u][1], pa[u][2], pa[u][3], vv.z, vv.w);
            }
        }
    }

    // ---- epilogue: quad-reduce l, store UNNORMALIZED partials ----
    ls0 += __shfl_xor_sync(0xffffffffu, ls0, 1);
    ls0 += __shfl_xor_sync(0xffffffffu, ls0, 2);
    ls1 += __shfl_xor_sync(0xffffffffu, ls1, 1);
    ls1 += __shfl_xor_sync(0xffffffffu, ls1, 2);

    const int row0 = bx * 64 + w * 16 + g;
    float* Ob = Op + ((size_t)(z * NB + b) * NTOK + row0) * DH;
    if (t == 0) {
        float* Lb = Lp + (size_t)(z * NB + b) * NTOK + row0;
        Lb[0] = ls0;
        Lb[8] = ls1;
    }
#pragma unroll
    for (int dt = 0; dt < 16; dt++) {
        *(float2*)(Ob + dt * 8 + 2 * t)            = make_float2(o[dt][0], o[dt][1]);
        *(float2*)(Ob + 8 * DH + dt * 8 + 2 * t)   = make_float2(o[dt][2], o[dt][3]);
    }
}

// ---------------------------------------------------------------------------
// Final 1x1 conv with fused partial merge:
//   O_attn[n][d] = (o0+o1)[n][d] / (l0+l1)[n];  out = wo @ O_attn + bo + x_lower
// ---------------------------------------------------------------------------
__global__ __launch_bounds__(256) void proj_out(
    const float* __restrict__ o0, const float* __restrict__ o1,
    const float* __restrict__ l0, const float* __restrict__ l1,
    const float* __restrict__ w,  const float* __restrict__ bias,
    const float* __restrict__ res, float* __restrict__ out)
{
    __shared__ float xs[16][256];
    __shared__ float ws[32][16];
    __shared__ float rl[256];          // 1/(l0+l1) for the 256 tokens this block touches
    const int b = blockIdx.z, c0 = blockIdx.y * 32, s0 = blockIdx.x * 256;
    const int tid = threadIdx.x, tx = tid & 63, ty = tid >> 6;

    {   // token for entry (k, e): n = k*32 + (s0>>7) + e
        int k = tid >> 1, e = tid & 1;
        int n = k * 32 + (s0 >> 7) + e;
        size_t li = (size_t)b * NTOK + n;
        rl[tid] = 1.0f / (l0[li] + l1[li]);
    }

    float acc[8][4];
#pragma unroll
    for (int i = 0; i < 8; i++)
#pragma unroll
        for (int j = 0; j < 4; j++) acc[i][j] = 0.f;

    const size_t xbase = (size_t)b * 128 * HW;

    for (int k0 = 0; k0 < 128; k0 += 16) {
        __syncthreads();
#pragma unroll
        for (int t = 0; t < 4; t++) {
            int f = tid + 256 * t, r = f >> 6, c4 = (f & 63) << 2;
            size_t idx = xbase + (size_t)(k0 + r) * HW + s0 + c4;
            float4 a = *(const float4*)(o0 + idx);
            float4 bb = *(const float4*)(o1 + idx);
            float sc = rl[(k0 + r) * 2 + (c4 >> 7)];
            a.x = (a.x + bb.x) * sc; a.y = (a.y + bb.y) * sc;
            a.z = (a.z + bb.z) * sc; a.w = (a.w + bb.w) * sc;
            *(float4*)&xs[r][c4] = a;
        }
#pragma unroll
        for (int t = 0; t < 2; t++) {
            int f = tid + 256 * t;
            ws[f >> 4][f & 15] = w[(size_t)(c0 + (f >> 4)) * 128 + k0 + (f & 15)];
        }
        __syncthreads();
#pragma unroll
        for (int k = 0; k < 16; k++) {
            float4 xv = *(float4*)&xs[k][tx << 2];
#pragma unroll
            for (int cc = 0; cc < 8; cc++) {
                float wv = ws[ty * 8 + cc][k];
                acc[cc][0] = fmaf(wv, xv.x, acc[cc][0]);
                acc[cc][1] = fmaf(wv, xv.y, acc[cc][1]);
                acc[cc][2] = fmaf(wv, xv.z, acc[cc][2]);
                acc[cc][3] = fmaf(wv, xv.w, acc[cc][3]);
            }
        }
    }

#pragma unroll
    for (int cc = 0; cc < 8; cc++) {
        const int c = c0 + ty * 8 + cc;
        const float bv = bias[c];
        const int s = s0 + (tx << 2);
        float4 rv = *(const float4*)(res + ((size_t)b * DH + c) * HW + s);
        float4 o;
        o.x = acc[cc][0] + bv + rv.x; o.y = acc[cc][1] + bv + rv.y;
        o.z = acc[cc][2] + bv + rv.z; o.w = acc[cc][3] + bv + rv.w;
        *(float4*)(out + ((size_t)b * DH + c) * HW + s) = o;
    }
}

static const int FLASH_SMEM = 3 * 4096 * 4;  // 48 KB

extern "C" void kernel_launch(void* const* d_in, const int* in_sizes, int n_in,
                              void* d_out, int out_size)
{
    const float* x_upper = (const float*)d_in[0];
    const float* x_lower = (const float*)d_in[1];
    const float* wq = (const float*)d_in[2];
    const float* bq = (const float*)d_in[3];
    const float* wk = (const float*)d_in[4];
    const float* bk = (const float*)d_in[5];
    const float* wv = (const float*)d_in[6];
    const float* bv = (const float*)d_in[7];
    const float* wo = (const float*)d_in[8];
    const float* bo = (const float*)d_in[9];
    float* out = (float*)d_out;

    uint32_t *Qp, *Kp, *Vp; float *Op, *Lpb;
    cudaGetSymbolAddress((void**)&Qp, g_Q);
    cudaGetSymbolAddress((void**)&Kp, g_K);
    cudaGetSymbolAddress((void**)&Vp, g_V);
    cudaGetSymbolAddress((void**)&Op, g_O);
    cudaGetSymbolAddress((void**)&Lpb, g_L);

    cudaFuncSetAttribute(flash_kernel,
                         cudaFuncAttributeMaxDynamicSharedMemorySize, FLASH_SMEM);

    proj_qkv<<<dim3(16, 4, 12), 256>>>(x_upper, x_lower, wq, bq, wk, bk, wv, bv,
                                       Qp, Kp, Vp);

    flash_kernel<<<dim3(64, NB, 2), 128, FLASH_SMEM>>>(
        (const uint4*)Qp, (const char*)Kp, (const char*)Vp, Op, Lpb);

    const float* o0 = Op;
    const float* o1 = Op + (size_t)NB * NTOK * DH;
    const float* l0 = Lpb;
    const float* l1 = Lpb + (size_t)NB * NTOK;
    proj_out<<<dim3(16, 4, 4), 256>>>(o0, o1, l0, l1, wo, bo, x_lower, out);
}

// round 9
// speedup vs baseline: 1.0127x; 1.0127x over previous
#include <cuda_runtime.h>
#include <math.h>
#include <stdint.h>

#define NB   4
#define HW   4096
#define DH   128
#define NTOK 4096

// Scratch (device globals; allocation-free).
// Q: A-frag m16n8k32 [b][mt(256)][ks(4)][lane(32)][4 u32]
// K: paired B-frag   [b][tile(64)][ntp(4)][ks(4)][lane(32)][4 u32] (8 KB/tile)
// V: paired B-frag   [b][tile(64)][dtp(8)][u(2)][lane(32)][4 u32]  (8 KB/tile)
//    key order pi-permuted so P C-frags pack directly into fp8 A-frags.
// O partials: [z(2)][b][n][d] fp32 unnormalized;  L partials: [z(2)][b][n].
__device__ uint32_t g_Q[NB * 131072];
__device__ uint32_t g_K[NB * 131072];
__device__ uint32_t g_V[NB * 131072];
__device__ float    g_O[2 * NB * NTOK * DH];
__device__ float    g_L[2 * NB * NTOK];

// log2(e)/sqrt(128): Q pre-scale so softmax runs in exp2 domain.
#define QSCALE (0.08838834764831845f * 1.4426950408889634f)

__device__ __forceinline__ float ex2f(float x) {
    float y; asm("ex2.approx.f32 %0, %1;" : "=f"(y) : "f"(x)); return y;
}
__device__ __forceinline__ uint32_t pack4_e4m3(float f0, float f1, float f2, float f3) {
    uint32_t r;
    asm("{\n\t.reg .b16 lo, hi;\n\t"
        "cvt.rn.satfinite.e4m3x2.f32 lo, %2, %1;\n\t"
        "cvt.rn.satfinite.e4m3x2.f32 hi, %4, %3;\n\t"
        "mov.b32 %0, {lo, hi};\n\t}"
        : "=r"(r) : "f"(f0), "f"(f1), "f"(f2), "f"(f3));
    return r;
}
__device__ __forceinline__ uint32_t e4m3_byte(float x) {
    uint16_t h;
    asm("{\n\t.reg .b16 t;\n\tcvt.rn.satfinite.e4m3x2.f32 t, %1, %1;\n\tmov.b16 %0, t;\n\t}"
        : "=h"(h) : "f"(x));
    return (uint32_t)(h & 0xFF);
}
__device__ __forceinline__ void mma_e4m3(float* d,
    uint32_t a0, uint32_t a1, uint32_t a2, uint32_t a3, uint32_t b0, uint32_t b1)
{
    asm volatile(
        "mma.sync.aligned.m16n8k32.row.col.f32.e4m3.e4m3.f32 "
        "{%0,%1,%2,%3},{%4,%5,%6,%7},{%8,%9},{%0,%1,%2,%3};"
        : "+f"(d[0]), "+f"(d[1]), "+f"(d[2]), "+f"(d[3])
        : "r"(a0), "r"(a1), "r"(a2), "r"(a3), "r"(b0), "r"(b1));
}
__device__ __forceinline__ void mma_e4m3_init(float* d,
    uint32_t a0, uint32_t a1, uint32_t a2, uint32_t a3, uint32_t b0, uint32_t b1)
{
    asm volatile(
        "mma.sync.aligned.m16n8k32.row.col.f32.e4m3.e4m3.f32 "
        "{%0,%1,%2,%3},{%4,%5,%6,%7},{%8,%9},{%10,%11,%12,%13};"
        : "=f"(d[0]), "=f"(d[1]), "=f"(d[2]), "=f"(d[3])
        : "r"(a0), "r"(a1), "r"(a2), "r"(a3), "r"(b0), "r"(b1),
          "f"(0.f), "f"(0.f), "f"(0.f), "f"(0.f));
}
__device__ __forceinline__ void cp_async16(void* smem_dst, const void* gmem_src) {
    uint32_t s = (uint32_t)__cvta_generic_to_shared(smem_dst);
    asm volatile("cp.async.cg.shared.global [%0], [%1], 16;\n" :: "r"(s), "l"(gmem_src));
}
#define CP_COMMIT() asm volatile("cp.async.commit_group;\n" ::: "memory")
template<int N> __device__ __forceinline__ void cp_wait() {
    asm volatile("cp.async.wait_group %0;\n" :: "n"(N) : "memory");
}

// ---------------------------------------------------------------------------
// Merged Q/K/V 1x1-conv projection (proven correct, rounds 7-8).
// ---------------------------------------------------------------------------
__global__ __launch_bounds__(256) void proj_qkv(
    const float* __restrict__ xu, const float* __restrict__ xl,
    const float* __restrict__ wq, const float* __restrict__ bq,
    const float* __restrict__ wk, const float* __restrict__ bk,
    const float* __restrict__ wv, const float* __restrict__ bv,
    uint32_t* __restrict__ Qo, uint32_t* __restrict__ Ko,
    uint32_t* __restrict__ Vo)
{
    __shared__ float xs[16][256];
    __shared__ float ws[32][16];

    const int m  = blockIdx.z % 3;
    const int b  = blockIdx.z / 3;
    const int CIN = (m == 0) ? 64 : 128;
    const float* x    = (m == 0) ? (xu + (size_t)b * 64 * HW)
                                 : (xl + (size_t)b * 128 * HW);
    const float* w    = (m == 0) ? wq : (m == 1) ? wk : wv;
    const float* bias = (m == 0) ? bq : (m == 1) ? bk : bv;

    const int c0 = blockIdx.y * 32, s0 = blockIdx.x * 256;
    const int tid = threadIdx.x, tx = tid & 63, ty = tid >> 6;

    float acc[8][4];
#pragma unroll
    for (int i = 0; i < 8; i++)
#pragma unroll
        for (int j = 0; j < 4; j++) acc[i][j] = 0.f;

    for (int k0 = 0; k0 < CIN; k0 += 16) {
        __syncthreads();
#pragma unroll
        for (int t = 0; t < 4; t++) {
            int f = tid + 256 * t, r = f >> 6, c4 = (f & 63) << 2;
            *(float4*)&xs[r][c4] = *(const float4*)(x + (size_t)(k0 + r) * HW + s0 + c4);
        }
#pragma unroll
        for (int t = 0; t < 2; t++) {
            int f = tid + 256 * t;
            ws[f >> 4][f & 15] = w[(size_t)(c0 + (f >> 4)) * CIN + k0 + (f & 15)];
        }
        __syncthreads();
#pragma unroll
        for (int k = 0; k < 16; k++) {
            float4 xv = *(float4*)&xs[k][tx << 2];
#pragma unroll
            for (int cc = 0; cc < 8; cc++) {
                float wv = ws[ty * 8 + cc][k];
                acc[cc][0] = fmaf(wv, xv.x, acc[cc][0]);
                acc[cc][1] = fmaf(wv, xv.y, acc[cc][1]);
                acc[cc][2] = fmaf(wv, xv.z, acc[cc][2]);
                acc[cc][3] = fmaf(wv, xv.w, acc[cc][3]);
            }
        }
    }

#pragma unroll
    for (int cc = 0; cc < 8; cc++) {
        const int c = c0 + ty * 8 + cc;
        const float bv_ = bias[c];
        const int s = s0 + (tx << 2);
        float v0 = acc[cc][0] + bv_, v1 = acc[cc][1] + bv_;
        float v2 = acc[cc][2] + bv_, v3 = acc[cc][3] + bv_;
        const int d0 = s & 127;
        const int n  = c * 32 + (s >> 7);
        const int ks = d0 >> 5, dd = d0 & 31;
        const int h = dd >> 4, t = (dd >> 2) & 3;

        if (m == 0) {
            int mt = n >> 4, r = n & 15;
            int g = r & 7, hi = r >> 3;
            size_t idx = (((size_t)b * 256 + mt) * 4 + ks) * 128
                       + (g * 4 + t) * 4 + hi + 2 * h;
            Qo[idx] = pack4_e4m3(v0 * QSCALE, v1 * QSCALE, v2 * QSCALE, v3 * QSCALE);
        } else if (m == 1) {
            int tile = n >> 6, j = n & 63;
            int nt = j >> 3, g = j & 7, ntp = nt >> 1, odd = nt & 1;
            size_t idx = (size_t)b * 131072 + (size_t)tile * 2048
                       + ((ntp * 4 + ks) * 32 + g * 4 + t) * 4 + odd * 2 + h;
            Ko[idx] = pack4_e4m3(v0, v1, v2, v3);
        } else {
            int tile = n >> 6, j = n & 63;
            int u  = j >> 5, jl = j & 31;
            int hv = jl >> 4, cpv = (jl >> 3) & 1, tv = (jl >> 1) & 3, c1 = jl & 1;
            int cv = cpv * 2 + c1;
            char* base = (char*)Vo + (size_t)b * 524288 + (size_t)tile * 8192;
            float vv[4] = {v0, v1, v2, v3};
#pragma unroll
            for (int q4 = 0; q4 < 4; q4++) {
                int d = d0 + q4;
                int dtp = d >> 4, odd = (d >> 3) & 1, g = d & 7;
                base[(((dtp * 2 + u) * 32 + g * 4 + tv) * 4 + odd * 2 + hv) * 4 + cv] =
                    (char)e4m3_byte(vv[q4]);
            }
        }
    }
}

// ---------------------------------------------------------------------------
// fp8 flash, KV-split z in {0,1}. BM=64, 128 threads.
// __launch_bounds__(128, 3): <=170 regs (no spills) -> 3 CTAs/SM.
// Writes UNNORMALIZED o-partials + l-partials; merged in proj_out.
// ---------------------------------------------------------------------------
__global__ __launch_bounds__(128, 3) void flash_kernel(
    const uint4* __restrict__ Qg, const char* __restrict__ Kg_,
    const char* __restrict__ Vg_, float* __restrict__ Op,
    float* __restrict__ Lp)
{
    extern __shared__ uint32_t sm[];   // 3 stages x (K 2048 u32 + V 2048 u32)

    const int b = blockIdx.y, bx = blockIdx.x, z = blockIdx.z;
    const int tid = threadIdx.x, w = tid >> 5, lane = tid & 31;
    const int g = lane >> 2, t = lane & 3;

    const char* Kg = Kg_ + (size_t)b * 524288 + (size_t)z * 32 * 8192;
    const char* Vg = Vg_ + (size_t)b * 524288 + (size_t)z * 32 * 8192;

    auto issueKV = [&](int i) {
        uint32_t st = (uint32_t)(i % 3) * 4096;
        const char* kg = Kg + (size_t)i * 8192;
        const char* vg = Vg + (size_t)i * 8192;
#pragma unroll
        for (int tt = 0; tt < 4; tt++) {
            int f = (tid + 128 * tt) * 16;
            cp_async16((char*)(sm + st) + f, kg + f);
        }
#pragma unroll
        for (int tt = 0; tt < 4; tt++) {
            int f = (tid + 128 * tt) * 16;
            cp_async16((char*)(sm + st + 2048) + f, vg + f);
        }
        CP_COMMIT();
    };
    issueKV(0); issueKV(1);

    // Q A-frags (4 k32 chunks) -> registers
    uint4 q[4];
    {
        const uint4* qp = Qg + ((size_t)(b * 256 + bx * 4 + w) * 4) * 32 + lane;
#pragma unroll
        for (int ks = 0; ks < 4; ks++) q[ks] = qp[ks * 32];
    }

    float o[16][4];
#pragma unroll
    for (int dt = 0; dt < 16; dt++)
#pragma unroll
        for (int j = 0; j < 4; j++) o[dt][j] = 0.f;
    float ls0 = 0.f, ls1 = 0.f;

    for (int i = 0; i < 32; i++) {
        cp_wait<1>();
        __syncthreads();
        if (i + 2 < 32) issueKV(i + 2); else CP_COMMIT();

        const uint32_t* ksb = sm + (uint32_t)(i % 3) * 4096;
        const uint32_t* vsb = ksb + 2048;

        uint32_t pa[2][4];
#pragma unroll
        for (int u = 0; u < 2; u++) {
            // ---- S half u: keys 32u..32u+31 (ntp 2u, 2u+1) ----
            float sf[4][4];
#pragma unroll
            for (int ks = 0; ks < 4; ks++) {
#pragma unroll
                for (int p = 0; p < 2; p++) {
                    const int ntp = 2 * u + p;
                    uint4 kb = *(const uint4*)(ksb + (ntp * 4 + ks) * 128 + lane * 4);
                    if (ks == 0) {
                        mma_e4m3_init(sf[p * 2],     q[ks].x, q[ks].y, q[ks].z, q[ks].w, kb.x, kb.y);
                        mma_e4m3_init(sf[p * 2 + 1], q[ks].x, q[ks].y, q[ks].z, q[ks].w, kb.z, kb.w);
                    } else {
                        mma_e4m3(sf[p * 2],     q[ks].x, q[ks].y, q[ks].z, q[ks].w, kb.x, kb.y);
                        mma_e4m3(sf[p * 2 + 1], q[ks].x, q[ks].y, q[ks].z, q[ks].w, kb.z, kb.w);
                    }
                }
            }
            // ---- softmax (no max, exp2) + fp8 P A-frag pack ----
            float e[4][4];
#pragma unroll
            for (int k = 0; k < 4; k++) {
                e[k][0] = ex2f(sf[k][0]); e[k][1] = ex2f(sf[k][1]);
                e[k][2] = ex2f(sf[k][2]); e[k][3] = ex2f(sf[k][3]);
                ls0 += e[k][0] + e[k][1];
                ls1 += e[k][2] + e[k][3];
            }
            pa[u][0] = pack4_e4m3(e[0][0], e[0][1], e[1][0], e[1][1]);
            pa[u][1] = pack4_e4m3(e[0][2], e[0][3], e[1][2], e[1][3]);
            pa[u][2] = pack4_e4m3(e[2][0], e[2][1], e[3][0], e[3][1]);
            pa[u][3] = pack4_e4m3(e[2][2], e[2][3], e[3][2], e[3][3]);
        }

        // ---- PV(i): o += P @ V (keys pi-permuted in V image) ----
#pragma unroll
        for (int u = 0; u < 2; u++) {
#pragma unroll
            for (int dtp = 0; dtp < 8; dtp++) {
                uint4 vv = *(const uint4*)(vsb + (dtp * 2 + u) * 128 + lane * 4);
                mma_e4m3(o[dtp * 2],     pa[u][0], pa[u][1], pa[u][2], pa[u][3], vv.x, vv.y);
                mma_e4m3(o[dtp * 2 + 1], pa[u][0], pa[u][1], pa[u][2], pa[u][3], vv.z, vv.w);
            }
        }
    }

    // ---- epilogue: quad-reduce l, store UNNORMALIZED partials ----
    ls0 += __shfl_xor_sync(0xffffffffu, ls0, 1);
    ls0 += __shfl_xor_sync(0xffffffffu, ls0, 2);
    ls1 += __shfl_xor_sync(0xffffffffu, ls1, 1);
    ls1 += __shfl_xor_sync(0xffffffffu, ls1, 2);

    const int row0 = bx * 64 + w * 16 + g;
    float* Ob = Op + ((size_t)(z * NB + b) * NTOK + row0) * DH;
    if (t == 0) {
        float* Lb = Lp + (size_t)(z * NB + b) * NTOK + row0;
        Lb[0] = ls0;
        Lb[8] = ls1;
    }
#pragma unroll
    for (int dt = 0; dt < 16; dt++) {
        *(float2*)(Ob + dt * 8 + 2 * t)            = make_float2(o[dt][0], o[dt][1]);
        *(float2*)(Ob + 8 * DH + dt * 8 + 2 * t)   = make_float2(o[dt][2], o[dt][3]);
    }
}

// ---------------------------------------------------------------------------
// Final 1x1 conv with fused partial merge:
//   O_attn[n][d] = (o0+o1)[n][d] / (l0+l1)[n];  out = wo @ O_attn + bo + x_lower
// ---------------------------------------------------------------------------
__global__ __launch_bounds__(256) void proj_out(
    const float* __restrict__ o0, const float* __restrict__ o1,
    const float* __restrict__ l0, const float* __restrict__ l1,
    const float* __restrict__ w,  const float* __restrict__ bias,
    const float* __restrict__ res, float* __restrict__ out)
{
    __shared__ float xs[16][256];
    __shared__ float ws[32][16];
    __shared__ float rl[256];          // 1/(l0+l1) for the 256 tokens this block touches
    const int b = blockIdx.z, c0 = blockIdx.y * 32, s0 = blockIdx.x * 256;
    const int tid = threadIdx.x, tx = tid & 63, ty = tid >> 6;

    {   // token for entry (k, e): n = k*32 + (s0>>7) + e
        int k = tid >> 1, e = tid & 1;
        int n = k * 32 + (s0 >> 7) + e;
        size_t li = (size_t)b * NTOK + n;
        rl[tid] = 1.0f / (l0[li] + l1[li]);
    }

    float acc[8][4];
#pragma unroll
    for (int i = 0; i < 8; i++)
#pragma unroll
        for (int j = 0; j < 4; j++) acc[i][j] = 0.f;

    const size_t xbase = (size_t)b * 128 * HW;

    for (int k0 = 0; k0 < 128; k0 += 16) {
        __syncthreads();
#pragma unroll
        for (int t = 0; t < 4; t++) {
            int f = tid + 256 * t, r = f >> 6, c4 = (f & 63) << 2;
            size_t idx = xbase + (size_t)(k0 + r) * HW + s0 + c4;
            float4 a = *(const float4*)(o0 + idx);
            float4 bb = *(const float4*)(o1 + idx);
            float sc = rl[(k0 + r) * 2 + (c4 >> 7)];
            a.x = (a.x + bb.x) * sc; a.y = (a.y + bb.y) * sc;
            a.z = (a.z + bb.z) * sc; a.w = (a.w + bb.w) * sc;
            *(float4*)&xs[r][c4] = a;
        }
#pragma unroll
        for (int t = 0; t < 2; t++) {
            int f = tid + 256 * t;
            ws[f >> 4][f & 15] = w[(size_t)(c0 + (f >> 4)) * 128 + k0 + (f & 15)];
        }
        __syncthreads();
#pragma unroll
        for (int k = 0; k < 16; k++) {
            float4 xv = *(float4*)&xs[k][tx << 2];
#pragma unroll
            for (int cc = 0; cc < 8; cc++) {
                float wv = ws[ty * 8 + cc][k];
                acc[cc][0] = fmaf(wv, xv.x, acc[cc][0]);
                acc[cc][1] = fmaf(wv, xv.y, acc[cc][1]);
                acc[cc][2] = fmaf(wv, xv.z, acc[cc][2]);
                acc[cc][3] = fmaf(wv, xv.w, acc[cc][3]);
            }
        }
    }

#pragma unroll
    for (int cc = 0; cc < 8; cc++) {
        const int c = c0 + ty * 8 + cc;
        const float bv = bias[c];
        const int s = s0 + (tx << 2);
        float4 rv = *(const float4*)(res + ((size_t)b * DH + c) * HW + s);
        float4 o;
        o.x = acc[cc][0] + bv + rv.x; o.y = acc[cc][1] + bv + rv.y;
        o.z = acc[cc][2] + bv + rv.z; o.w = acc[cc][3] + bv + rv.w;
        *(float4*)(out + ((size_t)b * DH + c) * HW + s) = o;
    }
}

static const int FLASH_SMEM = 3 * 4096 * 4;  // 48 KB

extern "C" void kernel_launch(void* const* d_in, const int* in_sizes, int n_in,
                              void* d_out, int out_size)
{
    const float* x_upper = (const float*)d_in[0];
    const float* x_lower = (const float*)d_in[1];
    const float* wq = (const float*)d_in[2];
    const float* bq = (const float*)d_in[3];
    const float* wk = (const float*)d_in[4];
    const float* bk = (const float*)d_in[5];
    const float* wv = (const float*)d_in[6];
    const float* bv = (const float*)d_in[7];
    const float* wo = (const float*)d_in[8];
    const float* bo = (const float*)d_in[9];
    float* out = (float*)d_out;

    uint32_t *Qp, *Kp, *Vp; float *Op, *Lpb;
    cudaGetSymbolAddress((void**)&Qp, g_Q);
    cudaGetSymbolAddress((void**)&Kp, g_K);
    cudaGetSymbolAddress((void**)&Vp, g_V);
    cudaGetSymbolAddress((void**)&Op, g_O);
    cudaGetSymbolAddress((void**)&Lpb, g_L);

    cudaFuncSetAttribute(flash_kernel,
                         cudaFuncAttributeMaxDynamicSharedMemorySize, FLASH_SMEM);

    proj_qkv<<<dim3(16, 4, 12), 256>>>(x_upper, x_lower, wq, bq, wk, bk, wv, bv,
                                       Qp, Kp, Vp);

    flash_kernel<<<dim3(64, NB, 2), 128, FLASH_SMEM>>>(
        (const uint4*)Qp, (const char*)Kp, (const char*)Vp, Op, Lpb);

    const float* o0 = Op;
    const float* o1 = Op + (size_t)NB * NTOK * DH;
    const float* l0 = Lpb;
    const float* l1 = Lpb + (size_t)NB * NTOK;
    proj_out<<<dim3(16, 4, 4), 256>>>(o0, o1, l0, l1, wo, bo, x_lower, out);
}

// round 10
// speedup vs baseline: 1.2248x; 1.2094x over previous
#include <cuda_runtime.h>
#include <math.h>
#include <stdint.h>

#define NB   4
#define HW   4096
#define DH   128
#define NTOK 4096
#define QKV_U32 (NTOK * DH / 2)   // 262144 u32 (bf16x2) per batch

// Q: A-frag m16n8k16 [b][mt(256)][ks(8)][lane(32)][4]
// K: paired B-frag   [b][ntp(256)][ks(8)][lane(32)][4]
// V: paired B-frag   [b][js(256)][dtp(8)][lane(32)][4]  (r6 layouts)
// O: plain fp32 [b][n][d] (raw-view == NCHW flat), normalized.
__device__ uint32_t g_Q[NB * QKV_U32];
__device__ uint32_t g_K[NB * QKV_U32];
__device__ uint32_t g_V[NB * QKV_U32];
__device__ float    g_O[NB * NTOK * DH];

// log2(e)/sqrt(128): Q pre-scale so softmax runs in exp2 domain.
#define QSCALE (0.08838834764831845f * 1.4426950408889634f)

__device__ __forceinline__ uint32_t pack_bf16(float lo, float hi) {
    uint32_t r; asm("cvt.rn.bf16x2.f32 %0, %1, %2;" : "=r"(r) : "f"(hi), "f"(lo)); return r;
}
__device__ __forceinline__ uint16_t bf16_bits(float x) {
    uint16_t r;
    asm("{.reg .b16 lo, hi; mov.b32 {lo, hi}, %1; cvt.rn.bf16.f32 hi, %1; mov.b16 %0, hi;}"
        : "=h"(r) : "f"(x));
    return r;
}
__device__ __forceinline__ float ex2f(float x) {
    float y; asm("ex2.approx.f32 %0, %1;" : "=f"(y) : "f"(x)); return y;
}
__device__ __forceinline__ uint32_t f2tf(float x) {
    uint32_t u; asm("cvt.rna.tf32.f32 %0, %1;" : "=r"(u) : "f"(x)); return u;
}
__device__ __forceinline__ void mma_tf32(float* d,
    uint32_t a0, uint32_t a1, uint32_t a2, uint32_t a3, uint32_t b0, uint32_t b1)
{
    asm volatile(
        "mma.sync.aligned.m16n8k8.row.col.f32.tf32.tf32.f32 "
        "{%0,%1,%2,%3},{%4,%5,%6,%7},{%8,%9},{%0,%1,%2,%3};"
        : "+f"(d[0]), "+f"(d[1]), "+f"(d[2]), "+f"(d[3])
        : "r"(a0), "r"(a1), "r"(a2), "r"(a3), "r"(b0), "r"(b1));
}
__device__ __forceinline__ void mma_bf16(float* d,
    uint32_t a0, uint32_t a1, uint32_t a2, uint32_t a3, uint32_t b0, uint32_t b1)
{
    asm volatile(
        "mma.sync.aligned.m16n8k16.row.col.f32.bf16.bf16.f32 "
        "{%0,%1,%2,%3},{%4,%5,%6,%7},{%8,%9},{%0,%1,%2,%3};"
        : "+f"(d[0]), "+f"(d[1]), "+f"(d[2]), "+f"(d[3])
        : "r"(a0), "r"(a1), "r"(a2), "r"(a3), "r"(b0), "r"(b1));
}
__device__ __forceinline__ void mma_bf16_init(float* d,
    uint32_t a0, uint32_t a1, uint32_t a2, uint32_t a3, uint32_t b0, uint32_t b1)
{
    asm volatile(
        "mma.sync.aligned.m16n8k16.row.col.f32.bf16.bf16.f32 "
        "{%0,%1,%2,%3},{%4,%5,%6,%7},{%8,%9},{%10,%11,%12,%13};"
        : "=f"(d[0]), "=f"(d[1]), "=f"(d[2]), "=f"(d[3])
        : "r"(a0), "r"(a1), "r"(a2), "r"(a3), "r"(b0), "r"(b1),
          "f"(0.f), "f"(0.f), "f"(0.f), "f"(0.f));
}
__device__ __forceinline__ void cp_async16(void* smem_dst, const void* gmem_src) {
    uint32_t s = (uint32_t)__cvta_generic_to_shared(smem_dst);
    asm volatile("cp.async.cg.shared.global [%0], [%1], 16;\n" :: "r"(s), "l"(gmem_src));
}
#define CP_COMMIT() asm volatile("cp.async.commit_group;\n" ::: "memory")
template<int N> __device__ __forceinline__ void cp_wait() {
    asm volatile("cp.async.wait_group %0;\n" :: "n"(N) : "memory");
}

// ---------------------------------------------------------------------------
// tf32 tensor-core QKV projection. CTA: C[128 cout x 128 spatial] = W @ X.
// blockIdx.y = b*3 + m. W -> tf32 A-frag images in smem (once); X double-
// buffered via cp.async. Epilogue: C -> smem (aliasing W) -> r6 emit code.
// ---------------------------------------------------------------------------
__global__ __launch_bounds__(256, 2) void proj_qkv_t(
    const float* __restrict__ xu, const float* __restrict__ xl,
    const float* __restrict__ wq, const float* __restrict__ bq,
    const float* __restrict__ wk, const float* __restrict__ bk,
    const float* __restrict__ wv, const float* __restrict__ bv,
    uint32_t* __restrict__ Qo, uint32_t* __restrict__ Ko,
    uint32_t* __restrict__ Vo)
{
    extern __shared__ uint32_t shm[];
    uint32_t* Wf  = shm;                       // [mt8][KS][lane32][4] tf32 (<=64KB)
    float*    Csm = (float*)shm;               // reused: [128][132] fp32 (67584B)
    float*    Xs  = (float*)(shm + 16896);     // 2 x [8][136] fp32 (8704B)

    const int m = blockIdx.y % 3, b = blockIdx.y / 3;
    const int CIN = (m == 0) ? 64 : 128;
    const int KS  = CIN >> 3;
    const int CLOG = (m == 0) ? 6 : 7;
    const float* x    = (m == 0) ? xu + (size_t)b * 64 * HW
                                 : xl + (size_t)b * 128 * HW;
    const float* w    = (m == 0) ? wq : (m == 1) ? wk : wv;
    const float* bias = (m == 0) ? bq : (m == 1) ? bk : bv;

    const int s0  = blockIdx.x * 128;
    const int tid = threadIdx.x, wp = tid >> 5, lane = tid & 31;
    const int g = lane >> 2, tq = lane & 3;
    const int wm = wp >> 2, wn = wp & 3;

    // W -> tf32 A-frag images
    for (int e = tid; e < (128 << CLOG); e += 256) {
        int mrow = e >> CLOG, k = e & (CIN - 1);
        int mt = mrow >> 4, r = mrow & 15, gg = r & 7, hi = r >> 3;
        int ks = k >> 3, kk = k & 7, c = kk & 3, ch = kk >> 2;
        Wf[((mt * KS + ks) * 32 + gg * 4 + c) * 4 + hi + 2 * ch] = f2tf(w[e]);
    }

    auto issueX = [&](int ks) {
        int row = tid >> 5, col = (tid & 31) * 4;
        cp_async16(Xs + (ks & 1) * 1088 + row * 136 + col,
                   x + (size_t)(ks * 8 + row) * HW + s0 + col);
        CP_COMMIT();
    };
    issueX(0); issueX(1);

    float acc[4][4][4];
#pragma unroll
    for (int i = 0; i < 4; i++)
#pragma unroll
        for (int j = 0; j < 4; j++)
#pragma unroll
            for (int k = 0; k < 4; k++) acc[i][j][k] = 0.f;

    __syncthreads();   // Wf visible

    for (int ks = 0; ks < KS; ks++) {
        cp_wait<1>();
        __syncthreads();
        const float* Xb = Xs + (ks & 1) * 1088;

        uint4 a[4];
#pragma unroll
        for (int mtl = 0; mtl < 4; mtl++)
            a[mtl] = *(const uint4*)&Wf[(((wm * 4 + mtl) * KS + ks) * 32 + lane) * 4];

#pragma unroll
        for (int ntl = 0; ntl < 4; ntl++) {
            int nn = wn * 32 + ntl * 8 + g;
            uint32_t b0 = f2tf(Xb[tq * 136 + nn]);
            uint32_t b1 = f2tf(Xb[(tq + 4) * 136 + nn]);
#pragma unroll
            for (int mtl = 0; mtl < 4; mtl++)
                mma_tf32(acc[mtl][ntl], a[mtl].x, a[mtl].y, a[mtl].z, a[mtl].w, b0, b1);
        }
        __syncthreads();
        if (ks + 2 < KS) issueX(ks + 2); else CP_COMMIT();
    }

    // C -> smem (aliases Wf; all A-frag reads complete)
    __syncthreads();
#pragma unroll
    for (int mtl = 0; mtl < 4; mtl++) {
        int row = wm * 64 + mtl * 16 + g;
#pragma unroll
        for (int ntl = 0; ntl < 4; ntl++) {
            int col = wn * 32 + ntl * 8 + 2 * tq;
            *(float2*)&Csm[row * 132 + col]       = make_float2(acc[mtl][ntl][0], acc[mtl][ntl][1]);
            *(float2*)&Csm[(row + 8) * 132 + col] = make_float2(acc[mtl][ntl][2], acc[mtl][ntl][3]);
        }
    }
    __syncthreads();

    // r6 emit (verbatim index math), reading C from smem
    uint16_t* outh = (uint16_t*)Vo;
#pragma unroll
    for (int cc = 0; cc < 16; cc++) {
        const int c  = cc * 8 + (tid >> 5);
        const int sl = (tid & 31) * 4;
        float4 vv4 = *(const float4*)&Csm[c * 132 + sl];
        const float bv_ = bias[c];
        float v0 = vv4.x + bv_, v1 = vv4.y + bv_, v2 = vv4.z + bv_, v3 = vv4.w + bv_;
        const int d0 = sl;
        const int n  = c * 32 + blockIdx.x;   // s0>>7 == blockIdx.x
        const int ks = d0 >> 4, kk = d0 & 15;
        if (m == 0) {
            int mt = n >> 4, r = n & 15;
            int grow = r & 7, hi = r >> 3;
            int ch = kk >> 3, t0 = (kk & 7) >> 1;
            size_t base = (((size_t)b * 256 + mt) * 8 + ks) * 128
                        + (grow * 4 + t0) * 4 + hi + 2 * ch;
            Qo[base]     = pack_bf16(v0 * QSCALE, v1 * QSCALE);
            Qo[base + 4] = pack_bf16(v2 * QSCALE, v3 * QSCALE);
        } else if (m == 1) {
            int ntp = n >> 4, odd = (n >> 3) & 1, gk = n & 7;
            int j = kk >> 3, t0 = (kk & 7) >> 1;
            size_t base = (((size_t)b * 256 + ntp) * 8 + ks) * 128
                        + (gk * 4 + t0) * 4 + odd * 2 + j;
            Ko[base]     = pack_bf16(v0, v1);
            Ko[base + 4] = pack_bf16(v2, v3);
        } else {
            int js = n >> 4, r = n & 15;
            int j = r >> 3, tv = (r & 7) >> 1, par = r & 1;
            float vv[4] = {v0, v1, v2, v3};
#pragma unroll
            for (int u = 0; u < 4; u++) {
                int d = d0 + u;
                int dtp = d >> 4, odd = (d >> 3) & 1, gd = d & 7;
                size_t u32i = (((size_t)b * 256 + js) * 8 + dtp) * 128
                            + (gd * 4 + tv) * 4 + odd * 2 + j;
                outh[u32i * 2 + par] = bf16_bits(vv[u]);
            }
        }
    }
}

// ---------------------------------------------------------------------------
// bf16 flash (round-6 verbatim): BM=128/CTA, BN=64, 8 warps, 4-stage cp.async,
// no-max exp2 softmax, Q in registers, paired B-frag K/V loads.
// ---------------------------------------------------------------------------
__global__ __launch_bounds__(256, 1) void flash_kernel(
    const uint4* __restrict__ Qg, const char* __restrict__ Kg_,
    const char* __restrict__ Vg_, float* __restrict__ O)
{
    extern __shared__ uint32_t sm[];   // 4 stages x (K 4096 u32 + V 4096 u32)

    const int b = blockIdx.y, bx = blockIdx.x;
    const int tid = threadIdx.x, w = tid >> 5, lane = tid & 31;
    const int g = lane >> 2, t = lane & 3;

    const char* Kg = Kg_ + (size_t)b * (QKV_U32 * 4);
    const char* Vg = Vg_ + (size_t)b * (QKV_U32 * 4);

    auto issueKV = [&](int i) {
        uint32_t st = (uint32_t)(i & 3) * 8192;
        const char* kg = Kg + (size_t)i * 16384;
        const char* vg = Vg + (size_t)i * 16384;
#pragma unroll
        for (int tt = 0; tt < 4; tt++) {
            int f = (tid + 256 * tt) * 16;
            cp_async16((char*)(sm + st) + f, kg + f);
        }
#pragma unroll
        for (int tt = 0; tt < 4; tt++) {
            int f = (tid + 256 * tt) * 16;
            cp_async16((char*)(sm + st + 4096) + f, vg + f);
        }
        CP_COMMIT();
    };
    issueKV(0); issueKV(1); issueKV(2);

    uint4 q[8];
    {
        const uint4* qp = Qg + ((size_t)(b * 256 + bx * 8 + w) * 8) * 32 + lane;
#pragma unroll
        for (int ks = 0; ks < 8; ks++) q[ks] = qp[ks * 32];
    }

    float o[16][4];
#pragma unroll
    for (int dt = 0; dt < 16; dt++)
#pragma unroll
        for (int j = 0; j < 4; j++) o[dt][j] = 0.f;
    float ls0 = 0.f, ls1 = 0.f;
    float sf[8][4];

    cp_wait<2>();
    __syncthreads();
    {
        const uint32_t* ksb = sm;
#pragma unroll
        for (int ks = 0; ks < 8; ks++) {
#pragma unroll
            for (int ntp = 0; ntp < 4; ntp++) {
                uint4 kb = *(const uint4*)(ksb + (ntp * 8 + ks) * 128 + lane * 4);
                if (ks == 0) {
                    mma_bf16_init(sf[ntp * 2],     q[ks].x, q[ks].y, q[ks].z, q[ks].w, kb.x, kb.y);
                    mma_bf16_init(sf[ntp * 2 + 1], q[ks].x, q[ks].y, q[ks].z, q[ks].w, kb.z, kb.w);
                } else {
                    mma_bf16(sf[ntp * 2],     q[ks].x, q[ks].y, q[ks].z, q[ks].w, kb.x, kb.y);
                    mma_bf16(sf[ntp * 2 + 1], q[ks].x, q[ks].y, q[ks].z, q[ks].w, kb.z, kb.w);
                }
            }
        }
    }

    for (int i = 0; i < 64; i++) {
        cp_wait<1>();
        __syncthreads();
        if (i + 3 < 64) issueKV(i + 3); else CP_COMMIT();

        const uint32_t* ksb = sm + (uint32_t)((i + 1) & 3) * 8192;
        const uint32_t* vsb = sm + (uint32_t)(i & 3) * 8192 + 4096;

        uint32_t p[16];
#pragma unroll
        for (int u = 0; u < 4; u++) {
            float a0 = ex2f(sf[2*u][0]),   a1 = ex2f(sf[2*u][1]);
            float a2 = ex2f(sf[2*u][2]),   a3 = ex2f(sf[2*u][3]);
            float b0 = ex2f(sf[2*u+1][0]), b1 = ex2f(sf[2*u+1][1]);
            float b2 = ex2f(sf[2*u+1][2]), b3 = ex2f(sf[2*u+1][3]);
            ls0 += a0 + a1 + b0 + b1;
            ls1 += a2 + a3 + b2 + b3;
            p[u*4+0] = pack_bf16(a0, a1);
            p[u*4+1] = pack_bf16(a2, a3);
            p[u*4+2] = pack_bf16(b0, b1);
            p[u*4+3] = pack_bf16(b2, b3);
        }

        if (i < 63) {
#pragma unroll
            for (int ks = 0; ks < 8; ks++) {
#pragma unroll
                for (int ntp = 0; ntp < 4; ntp++) {
                    uint4 kb = *(const uint4*)(ksb + (ntp * 8 + ks) * 128 + lane * 4);
                    if (ks == 0) {
                        mma_bf16_init(sf[ntp * 2],     q[ks].x, q[ks].y, q[ks].z, q[ks].w, kb.x, kb.y);
                        mma_bf16_init(sf[ntp * 2 + 1], q[ks].x, q[ks].y, q[ks].z, q[ks].w, kb.z, kb.w);
                    } else {
                        mma_bf16(sf[ntp * 2],     q[ks].x, q[ks].y, q[ks].z, q[ks].w, kb.x, kb.y);
                        mma_bf16(sf[ntp * 2 + 1], q[ks].x, q[ks].y, q[ks].z, q[ks].w, kb.z, kb.w);
                    }
                }
            }
        }

#pragma unroll
        for (int u = 0; u < 4; u++) {
#pragma unroll
            for (int dtp = 0; dtp < 8; dtp++) {
                uint4 vv = *(const uint4*)(vsb + (u * 8 + dtp) * 128 + lane * 4);
                mma_bf16(o[dtp * 2],     p[u*4+0], p[u*4+1], p[u*4+2], p[u*4+3], vv.x, vv.y);
                mma_bf16(o[dtp * 2 + 1], p[u*4+0], p[u*4+1], p[u*4+2], p[u*4+3], vv.z, vv.w);
            }
        }
    }

    ls0 += __shfl_xor_sync(0xffffffffu, ls0, 1);
    ls0 += __shfl_xor_sync(0xffffffffu, ls0, 2);
    ls1 += __shfl_xor_sync(0xffffffffu, ls1, 1);
    ls1 += __shfl_xor_sync(0xffffffffu, ls1, 2);
    const float inv0 = 1.0f / ls0, inv1 = 1.0f / ls1;

    float* Ob = O + ((size_t)(b * NTOK) + bx * 128 + w * 16) * DH;
#pragma unroll
    for (int dt = 0; dt < 16; dt++) {
        *(float2*)(Ob + g * DH + dt * 8 + 2 * t) =
            make_float2(o[dt][0] * inv0, o[dt][1] * inv0);
        *(float2*)(Ob + (g + 8) * DH + dt * 8 + 2 * t) =
            make_float2(o[dt][2] * inv1, o[dt][3] * inv1);
    }
}

// ---------------------------------------------------------------------------
// tf32 tensor-core final conv: out = wo @ O + bo + x_lower. Direct epilogue.
// ---------------------------------------------------------------------------
__global__ __launch_bounds__(256, 2) void proj_out_t(
    const float* __restrict__ Oin, const float* __restrict__ w,
    const float* __restrict__ bias, const float* __restrict__ res,
    float* __restrict__ out)
{
    extern __shared__ uint32_t shm[];
    uint32_t* Wf = shm;                       // [mt8][16][lane32][4] tf32 (64KB)
    float*    Xs = (float*)(shm + 16384);     // 2 x [8][136] fp32

    const int b  = blockIdx.y;
    const int s0 = blockIdx.x * 128;
    const int tid = threadIdx.x, wp = tid >> 5, lane = tid & 31;
    const int g = lane >> 2, tq = lane & 3;
    const int wm = wp >> 2, wn = wp & 3;

    const float* x = Oin + (size_t)b * 128 * HW;   // O raw-view: channel-major

    for (int e = tid; e < 128 * 128; e += 256) {
        int mrow = e >> 7, k = e & 127;
        int mt = mrow >> 4, r = mrow & 15, gg = r & 7, hi = r >> 3;
        int ks = k >> 3, kk = k & 7, c = kk & 3, ch = kk >> 2;
        Wf[((mt * 16 + ks) * 32 + gg * 4 + c) * 4 + hi + 2 * ch] = f2tf(w[e]);
    }

    auto issueX = [&](int ks) {
        int row = tid >> 5, col = (tid & 31) * 4;
        cp_async16(Xs + (ks & 1) * 1088 + row * 136 + col,
                   x + (size_t)(ks * 8 + row) * HW + s0 + col);
        CP_COMMIT();
    };
    issueX(0); issueX(1);

    float acc[4][4][4];
#pragma unroll
    for (int i = 0; i < 4; i++)
#pragma unroll
        for (int j = 0; j < 4; j++)
#pragma unroll
            for (int k = 0; k < 4; k++) acc[i][j][k] = 0.f;

    __syncthreads();

    for (int ks = 0; ks < 16; ks++) {
        cp_wait<1>();
        __syncthreads();
        const float* Xb = Xs + (ks & 1) * 1088;

        uint4 a[4];
#pragma unroll
        for (int mtl = 0; mtl < 4; mtl++)
            a[mtl] = *(const uint4*)&Wf[(((wm * 4 + mtl) * 16 + ks) * 32 + lane) * 4];

#pragma unroll
        for (int ntl = 0; ntl < 4; ntl++) {
            int nn = wn * 32 + ntl * 8 + g;
            uint32_t b0 = f2tf(Xb[tq * 136 + nn]);
            uint32_t b1 = f2tf(Xb[(tq + 4) * 136 + nn]);
#pragma unroll
            for (int mtl = 0; mtl < 4; mtl++)
                mma_tf32(acc[mtl][ntl], a[mtl].x, a[mtl].y, a[mtl].z, a[mtl].w, b0, b1);
        }
        __syncthreads();
        if (ks + 2 < 16) issueX(ks + 2); else CP_COMMIT();
    }

    // direct epilogue: bias + residual, coalesced float2 stores
#pragma unroll
    for (int mtl = 0; mtl < 4; mtl++) {
        int row0 = wm * 64 + mtl * 16 + g;
        float bv0 = bias[row0], bv1 = bias[row0 + 8];
#pragma unroll
        for (int ntl = 0; ntl < 4; ntl++) {
            int col = s0 + wn * 32 + ntl * 8 + 2 * tq;
            size_t i0 = ((size_t)b * 128 + row0) * HW + col;
            size_t i1 = ((size_t)b * 128 + row0 + 8) * HW + col;
            float2 r0 = *(const float2*)(res + i0);
            float2 r1 = *(const float2*)(res + i1);
            *(float2*)(out + i0) = make_float2(acc[mtl][ntl][0] + bv0 + r0.x,
                                               acc[mtl][ntl][1] + bv0 + r0.y);
            *(float2*)(out + i1) = make_float2(acc[mtl][ntl][2] + bv1 + r1.x,
                                               acc[mtl][ntl][3] + bv1 + r1.y);
        }
    }
}

static const int FLASH_SMEM = 4 * 8192 * 4;          // 128 KB
static const int QKV_SMEM   = 67584 + 8704;          // Csm/Wf + X db = 76288 B
static const int POUT_SMEM  = 65536 + 8704;          // Wf + X db = 74240 B

extern "C" void kernel_launch(void* const* d_in, const int* in_sizes, int n_in,
                              void* d_out, int out_size)
{
    const float* x_upper = (const float*)d_in[0];
    const float* x_lower = (const float*)d_in[1];
    const float* wq = (const float*)d_in[2];
    const float* bq = (const float*)d_in[3];
    const float* wk = (const float*)d_in[4];
    const float* bk = (const float*)d_in[5];
    const float* wv = (const float*)d_in[6];
    const float* bv = (const float*)d_in[7];
    const float* wo = (const float*)d_in[8];
    const float* bo = (const float*)d_in[9];
    float* out = (float*)d_out;

    uint32_t *Qp, *Kp, *Vp; float* Op;
    cudaGetSymbolAddress((void**)&Qp, g_Q);
    cudaGetSymbolAddress((void**)&Kp, g_K);
    cudaGetSymbolAddress((void**)&Vp, g_V);
    cudaGetSymbolAddress((void**)&Op, g_O);

    cudaFuncSetAttribute(flash_kernel,
                         cudaFuncAttributeMaxDynamicSharedMemorySize, FLASH_SMEM);
    cudaFuncSetAttribute(proj_qkv_t,
                         cudaFuncAttributeMaxDynamicSharedMemorySize, QKV_SMEM);
    cudaFuncSetAttribute(proj_out_t,
                         cudaFuncAttributeMaxDynamicSharedMemorySize, POUT_SMEM);

    proj_qkv_t<<<dim3(32, 12), 256, QKV_SMEM>>>(x_upper, x_lower,
                                                wq, bq, wk, bk, wv, bv,
                                                Qp, Kp, Vp);

    flash_kernel<<<dim3(NTOK / 128, NB), 256, FLASH_SMEM>>>(
        (const uint4*)Qp, (const char*)Kp, (const char*)Vp, Op);

    proj_out_t<<<dim3(32, 4), 256, POUT_SMEM>>>(Op, wo, bo, x_lower, out);
}

// round 11
// speedup vs baseline: 1.2274x; 1.0021x over previous
#include <cuda_runtime.h>
#include <math.h>
#include <stdint.h>

#define NB   4
#define HW   4096
#define DH   128
#define NTOK 4096
#define QKV_U32 (NTOK * DH / 2)   // 262144 u32 (bf16x2) per batch

// Q: A-frag m16n8k16 [b][mt(256)][ks(8)][lane(32)][4]
// K: paired B-frag   [b][ntp(256)][ks(8)][lane(32)][4]
// V: paired B-frag   [b][js(256)][dtp(8)][lane(32)][4]  (r6 layouts)
// O: plain fp32 [b][n][d] (raw-view == NCHW flat), normalized.
__device__ uint32_t g_Q[NB * QKV_U32];
__device__ uint32_t g_K[NB * QKV_U32];
__device__ uint32_t g_V[NB * QKV_U32];
__device__ float    g_O[NB * NTOK * DH];

// log2(e)/sqrt(128): Q pre-scale so softmax runs in exp2 domain.
#define QSCALE (0.08838834764831845f * 1.4426950408889634f)

__device__ __forceinline__ uint32_t pack_bf16(float lo, float hi) {
    uint32_t r; asm("cvt.rn.bf16x2.f32 %0, %1, %2;" : "=r"(r) : "f"(hi), "f"(lo)); return r;
}
__device__ __forceinline__ uint16_t bf16_bits(float x) {
    uint16_t r;
    asm("{.reg .b16 lo, hi; mov.b32 {lo, hi}, %1; cvt.rn.bf16.f32 hi, %1; mov.b16 %0, hi;}"
        : "=h"(r) : "f"(x));
    return r;
}
__device__ __forceinline__ float ex2f(float x) {
    float y; asm("ex2.approx.f32 %0, %1;" : "=f"(y) : "f"(x)); return y;
}
__device__ __forceinline__ uint32_t f2tf(float x) {
    uint32_t u; asm("cvt.rna.tf32.f32 %0, %1;" : "=r"(u) : "f"(x)); return u;
}
__device__ __forceinline__ void mma_tf32(float* d,
    uint32_t a0, uint32_t a1, uint32_t a2, uint32_t a3, uint32_t b0, uint32_t b1)
{
    asm volatile(
        "mma.sync.aligned.m16n8k8.row.col.f32.tf32.tf32.f32 "
        "{%0,%1,%2,%3},{%4,%5,%6,%7},{%8,%9},{%0,%1,%2,%3};"
        : "+f"(d[0]), "+f"(d[1]), "+f"(d[2]), "+f"(d[3])
        : "r"(a0), "r"(a1), "r"(a2), "r"(a3), "r"(b0), "r"(b1));
}
__device__ __forceinline__ void mma_bf16(float* d,
    uint32_t a0, uint32_t a1, uint32_t a2, uint32_t a3, uint32_t b0, uint32_t b1)
{
    asm volatile(
        "mma.sync.aligned.m16n8k16.row.col.f32.bf16.bf16.f32 "
        "{%0,%1,%2,%3},{%4,%5,%6,%7},{%8,%9},{%0,%1,%2,%3};"
        : "+f"(d[0]), "+f"(d[1]), "+f"(d[2]), "+f"(d[3])
        : "r"(a0), "r"(a1), "r"(a2), "r"(a3), "r"(b0), "r"(b1));
}
__device__ __forceinline__ void mma_bf16_init(float* d,
    uint32_t a0, uint32_t a1, uint32_t a2, uint32_t a3, uint32_t b0, uint32_t b1)
{
    asm volatile(
        "mma.sync.aligned.m16n8k16.row.col.f32.bf16.bf16.f32 "
        "{%0,%1,%2,%3},{%4,%5,%6,%7},{%8,%9},{%10,%11,%12,%13};"
        : "=f"(d[0]), "=f"(d[1]), "=f"(d[2]), "=f"(d[3])
        : "r"(a0), "r"(a1), "r"(a2), "r"(a3), "r"(b0), "r"(b1),
          "f"(0.f), "f"(0.f), "f"(0.f), "f"(0.f));
}
__device__ __forceinline__ void cp_async16(void* smem_dst, const void* gmem_src) {
    uint32_t s = (uint32_t)__cvta_generic_to_shared(smem_dst);
    asm volatile("cp.async.cg.shared.global [%0], [%1], 16;\n" :: "r"(s), "l"(gmem_src));
}
#define CP_COMMIT() asm volatile("cp.async.commit_group;\n" ::: "memory")
template<int N> __device__ __forceinline__ void cp_wait() {
    asm volatile("cp.async.wait_group %0;\n" :: "n"(N) : "memory");
}

// ---------------------------------------------------------------------------
// tf32 QKV projection. C[128 cout x 128 spatial] = W @ X per CTA.
// 4-stage X pipeline (16 k-rows/stage), one sync per step, W-conv overlapped
// with the primed X loads. Epilogue: C -> smem (alias Wf) -> r6 emit.
// ---------------------------------------------------------------------------
__global__ __launch_bounds__(256, 2) void proj_qkv_t(
    const float* __restrict__ xu, const float* __restrict__ xl,
    const float* __restrict__ wq, const float* __restrict__ bq,
    const float* __restrict__ wk, const float* __restrict__ bk,
    const float* __restrict__ wv, const float* __restrict__ bv,
    uint32_t* __restrict__ Qo, uint32_t* __restrict__ Ko,
    uint32_t* __restrict__ Vo)
{
    extern __shared__ uint32_t shm[];
    uint32_t* Wf  = shm;                       // [mt8][KS][lane32][4] tf32 (<=64KB)
    float*    Csm = (float*)shm;               // reused: [128][132] fp32 (67584B)
    float*    Xs  = (float*)(shm + 16896);     // 4 stages x [16][136] fp32 (34816B)

    const int m = blockIdx.y % 3, b = blockIdx.y / 3;
    const int CIN = (m == 0) ? 64 : 128;
    const int KS  = CIN >> 3;                  // k8 steps
    const int NK  = CIN >> 4;                  // k16 pipeline steps
    const int CLOG = (m == 0) ? 6 : 7;
    const float* x    = (m == 0) ? xu + (size_t)b * 64 * HW
                                 : xl + (size_t)b * 128 * HW;
    const float* w    = (m == 0) ? wq : (m == 1) ? wk : wv;
    const float* bias = (m == 0) ? bq : (m == 1) ? bk : bv;

    const int s0  = blockIdx.x * 128;
    const int tid = threadIdx.x, wp = tid >> 5, lane = tid & 31;
    const int g = lane >> 2, tq = lane & 3;
    const int wm = wp >> 2, wn = wp & 3;

    // prime 3 X stages FIRST (fly while W converts)
    auto issueX = [&](int j) {
        // 16 rows x 128 cols = 512 float4; 256 threads x 2
        float* dst = Xs + (j & 3) * 2176;
#pragma unroll
        for (int tt = 0; tt < 2; tt++) {
            int f = tid + 256 * tt;            // f in [0,512)
            int row = f >> 5, col = (f & 31) * 4;
            cp_async16(dst + row * 136 + col,
                       x + (size_t)(j * 16 + row) * HW + s0 + col);
        }
        CP_COMMIT();
    };
    issueX(0); issueX(1);
    if (NK > 2) issueX(2); else CP_COMMIT();

    // W -> tf32 A-frag images (overlapped with X loads)
    for (int e = tid; e < (128 << CLOG); e += 256) {
        int mrow = e >> CLOG, k = e & (CIN - 1);
        int mt = mrow >> 4, r = mrow & 15, gg = r & 7, hi = r >> 3;
        int ks = k >> 3, kk = k & 7, c = kk & 3, ch = kk >> 2;
        Wf[((mt * KS + ks) * 32 + gg * 4 + c) * 4 + hi + 2 * ch] = f2tf(w[e]);
    }

    float acc[4][4][4];
#pragma unroll
    for (int i = 0; i < 4; i++)
#pragma unroll
        for (int j = 0; j < 4; j++)
#pragma unroll
            for (int k = 0; k < 4; k++) acc[i][j][k] = 0.f;

    __syncthreads();   // Wf visible

    for (int j = 0; j < NK; j++) {
        cp_wait<2>();          // group j complete (j+1, j+2 may be pending)
        __syncthreads();
        if (j + 3 < NK) issueX(j + 3); else CP_COMMIT();
        const float* Xb = Xs + (j & 3) * 2176;

#pragma unroll
        for (int h = 0; h < 2; h++) {
            const int ks = j * 2 + h;
            uint4 a[4];
#pragma unroll
            for (int mtl = 0; mtl < 4; mtl++)
                a[mtl] = *(const uint4*)&Wf[(((wm * 4 + mtl) * KS + ks) * 32 + lane) * 4];
#pragma unroll
            for (int ntl = 0; ntl < 4; ntl++) {
                int nn = wn * 32 + ntl * 8 + g;
                uint32_t b0 = f2tf(Xb[(h * 8 + tq) * 136 + nn]);
                uint32_t b1 = f2tf(Xb[(h * 8 + tq + 4) * 136 + nn]);
#pragma unroll
                for (int mtl = 0; mtl < 4; mtl++)
                    mma_tf32(acc[mtl][ntl], a[mtl].x, a[mtl].y, a[mtl].z, a[mtl].w, b0, b1);
            }
        }
    }

    // C -> smem (aliases Wf; all A-frag reads complete)
    __syncthreads();
#pragma unroll
    for (int mtl = 0; mtl < 4; mtl++) {
        int row = wm * 64 + mtl * 16 + g;
#pragma unroll
        for (int ntl = 0; ntl < 4; ntl++) {
            int col = wn * 32 + ntl * 8 + 2 * tq;
            *(float2*)&Csm[row * 132 + col]       = make_float2(acc[mtl][ntl][0], acc[mtl][ntl][1]);
            *(float2*)&Csm[(row + 8) * 132 + col] = make_float2(acc[mtl][ntl][2], acc[mtl][ntl][3]);
        }
    }
    __syncthreads();

    // r6 emit (verbatim index math), reading C from smem
    uint16_t* outh = (uint16_t*)Vo;
#pragma unroll
    for (int cc = 0; cc < 16; cc++) {
        const int c  = cc * 8 + (tid >> 5);
        const int sl = (tid & 31) * 4;
        float4 vv4 = *(const float4*)&Csm[c * 132 + sl];
        const float bv_ = bias[c];
        float v0 = vv4.x + bv_, v1 = vv4.y + bv_, v2 = vv4.z + bv_, v3 = vv4.w + bv_;
        const int d0 = sl;
        const int n  = c * 32 + blockIdx.x;
        const int ks = d0 >> 4, kk = d0 & 15;
        if (m == 0) {
            int mt = n >> 4, r = n & 15;
            int grow = r & 7, hi = r >> 3;
            int ch = kk >> 3, t0 = (kk & 7) >> 1;
            size_t base = (((size_t)b * 256 + mt) * 8 + ks) * 128
                        + (grow * 4 + t0) * 4 + hi + 2 * ch;
            Qo[base]     = pack_bf16(v0 * QSCALE, v1 * QSCALE);
            Qo[base + 4] = pack_bf16(v2 * QSCALE, v3 * QSCALE);
        } else if (m == 1) {
            int ntp = n >> 4, odd = (n >> 3) & 1, gk = n & 7;
            int j = kk >> 3, t0 = (kk & 7) >> 1;
            size_t base = (((size_t)b * 256 + ntp) * 8 + ks) * 128
                        + (gk * 4 + t0) * 4 + odd * 2 + j;
            Ko[base]     = pack_bf16(v0, v1);
            Ko[base + 4] = pack_bf16(v2, v3);
        } else {
            int js = n >> 4, r = n & 15;
            int j = r >> 3, tv = (r & 7) >> 1, par = r & 1;
            float vv[4] = {v0, v1, v2, v3};
#pragma unroll
            for (int u = 0; u < 4; u++) {
                int d = d0 + u;
                int dtp = d >> 4, odd = (d >> 3) & 1, gd = d & 7;
                size_t u32i = (((size_t)b * 256 + js) * 8 + dtp) * 128
                            + (gd * 4 + tv) * 4 + odd * 2 + j;
                outh[u32i * 2 + par] = bf16_bits(vv[u]);
            }
        }
    }
}

// ---------------------------------------------------------------------------
// bf16 flash (round-6 verbatim; proven 112.7us): BM=128, BN=64, 8 warps,
// 4-stage cp.async, no-max exp2 softmax, Q in regs, paired B-frag K/V loads.
// ---------------------------------------------------------------------------
__global__ __launch_bounds__(256, 1) void flash_kernel(
    const uint4* __restrict__ Qg, const char* __restrict__ Kg_,
    const char* __restrict__ Vg_, float* __restrict__ O)
{
    extern __shared__ uint32_t sm[];

    const int b = blockIdx.y, bx = blockIdx.x;
    const int tid = threadIdx.x, w = tid >> 5, lane = tid & 31;
    const int g = lane >> 2, t = lane & 3;

    const char* Kg = Kg_ + (size_t)b * (QKV_U32 * 4);
    const char* Vg = Vg_ + (size_t)b * (QKV_U32 * 4);

    auto issueKV = [&](int i) {
        uint32_t st = (uint32_t)(i & 3) * 8192;
        const char* kg = Kg + (size_t)i * 16384;
        const char* vg = Vg + (size_t)i * 16384;
#pragma unroll
        for (int tt = 0; tt < 4; tt++) {
            int f = (tid + 256 * tt) * 16;
            cp_async16((char*)(sm + st) + f, kg + f);
        }
#pragma unroll
        for (int tt = 0; tt < 4; tt++) {
            int f = (tid + 256 * tt) * 16;
            cp_async16((char*)(sm + st + 4096) + f, vg + f);
        }
        CP_COMMIT();
    };
    issueKV(0); issueKV(1); issueKV(2);

    uint4 q[8];
    {
        const uint4* qp = Qg + ((size_t)(b * 256 + bx * 8 + w) * 8) * 32 + lane;
#pragma unroll
        for (int ks = 0; ks < 8; ks++) q[ks] = qp[ks * 32];
    }

    float o[16][4];
#pragma unroll
    for (int dt = 0; dt < 16; dt++)
#pragma unroll
        for (int j = 0; j < 4; j++) o[dt][j] = 0.f;
    float ls0 = 0.f, ls1 = 0.f;
    float sf[8][4];

    cp_wait<2>();
    __syncthreads();
    {
        const uint32_t* ksb = sm;
#pragma unroll
        for (int ks = 0; ks < 8; ks++) {
#pragma unroll
            for (int ntp = 0; ntp < 4; ntp++) {
                uint4 kb = *(const uint4*)(ksb + (ntp * 8 + ks) * 128 + lane * 4);
                if (ks == 0) {
                    mma_bf16_init(sf[ntp * 2],     q[ks].x, q[ks].y, q[ks].z, q[ks].w, kb.x, kb.y);
                    mma_bf16_init(sf[ntp * 2 + 1], q[ks].x, q[ks].y, q[ks].z, q[ks].w, kb.z, kb.w);
                } else {
                    mma_bf16(sf[ntp * 2],     q[ks].x, q[ks].y, q[ks].z, q[ks].w, kb.x, kb.y);
                    mma_bf16(sf[ntp * 2 + 1], q[ks].x, q[ks].y, q[ks].z, q[ks].w, kb.z, kb.w);
                }
            }
        }
    }

    for (int i = 0; i < 64; i++) {
        cp_wait<1>();
        __syncthreads();
        if (i + 3 < 64) issueKV(i + 3); else CP_COMMIT();

        const uint32_t* ksb = sm + (uint32_t)((i + 1) & 3) * 8192;
        const uint32_t* vsb = sm + (uint32_t)(i & 3) * 8192 + 4096;

        uint32_t p[16];
#pragma unroll
        for (int u = 0; u < 4; u++) {
            float a0 = ex2f(sf[2*u][0]),   a1 = ex2f(sf[2*u][1]);
            float a2 = ex2f(sf[2*u][2]),   a3 = ex2f(sf[2*u][3]);
            float b0 = ex2f(sf[2*u+1][0]), b1 = ex2f(sf[2*u+1][1]);
            float b2 = ex2f(sf[2*u+1][2]), b3 = ex2f(sf[2*u+1][3]);
            ls0 += a0 + a1 + b0 + b1;
            ls1 += a2 + a3 + b2 + b3;
            p[u*4+0] = pack_bf16(a0, a1);
            p[u*4+1] = pack_bf16(a2, a3);
            p[u*4+2] = pack_bf16(b0, b1);
            p[u*4+3] = pack_bf16(b2, b3);
        }

        if (i < 63) {
#pragma unroll
            for (int ks = 0; ks < 8; ks++) {
#pragma unroll
                for (int ntp = 0; ntp < 4; ntp++) {
                    uint4 kb = *(const uint4*)(ksb + (ntp * 8 + ks) * 128 + lane * 4);
                    if (ks == 0) {
                        mma_bf16_init(sf[ntp * 2],     q[ks].x, q[ks].y, q[ks].z, q[ks].w, kb.x, kb.y);
                        mma_bf16_init(sf[ntp * 2 + 1], q[ks].x, q[ks].y, q[ks].z, q[ks].w, kb.z, kb.w);
                    } else {
                        mma_bf16(sf[ntp * 2],     q[ks].x, q[ks].y, q[ks].z, q[ks].w, kb.x, kb.y);
                        mma_bf16(sf[ntp * 2 + 1], q[ks].x, q[ks].y, q[ks].z, q[ks].w, kb.z, kb.w);
                    }
                }
            }
        }

#pragma unroll
        for (int u = 0; u < 4; u++) {
#pragma unroll
            for (int dtp = 0; dtp < 8; dtp++) {
                uint4 vv = *(const uint4*)(vsb + (u * 8 + dtp) * 128 + lane * 4);
                mma_bf16(o[dtp * 2],     p[u*4+0], p[u*4+1], p[u*4+2], p[u*4+3], vv.x, vv.y);
                mma_bf16(o[dtp * 2 + 1], p[u*4+0], p[u*4+1], p[u*4+2], p[u*4+3], vv.z, vv.w);
            }
        }
    }

    ls0 += __shfl_xor_sync(0xffffffffu, ls0, 1);
    ls0 += __shfl_xor_sync(0xffffffffu, ls0, 2);
    ls1 += __shfl_xor_sync(0xffffffffu, ls1, 1);
    ls1 += __shfl_xor_sync(0xffffffffu, ls1, 2);
    const float inv0 = 1.0f / ls0, inv1 = 1.0f / ls1;

    float* Ob = O + ((size_t)(b * NTOK) + bx * 128 + w * 16) * DH;
#pragma unroll
    for (int dt = 0; dt < 16; dt++) {
        *(float2*)(Ob + g * DH + dt * 8 + 2 * t) =
            make_float2(o[dt][0] * inv0, o[dt][1] * inv0);
        *(float2*)(Ob + (g + 8) * DH + dt * 8 + 2 * t) =
            make_float2(o[dt][2] * inv1, o[dt][3] * inv1);
    }
}

// ---------------------------------------------------------------------------
// tf32 final conv, same 4-stage pipeline. out = wo @ O + bo + x_lower.
// ---------------------------------------------------------------------------
__global__ __launch_bounds__(256, 2) void proj_out_t(
    const float* __restrict__ Oin, const float* __restrict__ w,
    const float* __restrict__ bias, const float* __restrict__ res,
    float* __restrict__ out)
{
    extern __shared__ uint32_t shm[];
    uint32_t* Wf = shm;                       // [mt8][16][lane32][4] tf32 (64KB)
    float*    Xs = (float*)(shm + 16384);     // 4 stages x [16][136] fp32

    const int b  = blockIdx.y;
    const int s0 = blockIdx.x * 128;
    const int tid = threadIdx.x, wp = tid >> 5, lane = tid & 31;
    const int g = lane >> 2, tq = lane & 3;
    const int wm = wp >> 2, wn = wp & 3;

    const float* x = Oin + (size_t)b * 128 * HW;

    auto issueX = [&](int j) {
        float* dst = Xs + (j & 3) * 2176;
#pragma unroll
        for (int tt = 0; tt < 2; tt++) {
            int f = tid + 256 * tt;
            int row = f >> 5, col = (f & 31) * 4;
            cp_async16(dst + row * 136 + col,
                       x + (size_t)(j * 16 + row) * HW + s0 + col);
        }
        CP_COMMIT();
    };
    issueX(0); issueX(1); issueX(2);

    for (int e = tid; e < 128 * 128; e += 256) {
        int mrow = e >> 7, k = e & 127;
        int mt = mrow >> 4, r = mrow & 15, gg = r & 7, hi = r >> 3;
        int ks = k >> 3, kk = k & 7, c = kk & 3, ch = kk >> 2;
        Wf[((mt * 16 + ks) * 32 + gg * 4 + c) * 4 + hi + 2 * ch] = f2tf(w[e]);
    }

    float acc[4][4][4];
#pragma unroll
    for (int i = 0; i < 4; i++)
#pragma unroll
        for (int j = 0; j < 4; j++)
#pragma unroll
            for (int k = 0; k < 4; k++) acc[i][j][k] = 0.f;

    __syncthreads();

    for (int j = 0; j < 8; j++) {
        cp_wait<2>();
        __syncthreads();
        if (j + 3 < 8) issueX(j + 3); else CP_COMMIT();
        const float* Xb = Xs + (j & 3) * 2176;

#pragma unroll
        for (int h = 0; h < 2; h++) {
            const int ks = j * 2 + h;
            uint4 a[4];
#pragma unroll
            for (int mtl = 0; mtl < 4; mtl++)
                a[mtl] = *(const uint4*)&Wf[(((wm * 4 + mtl) * 16 + ks) * 32 + lane) * 4];
#pragma unroll
            for (int ntl = 0; ntl < 4; ntl++) {
                int nn = wn * 32 + ntl * 8 + g;
                uint32_t b0 = f2tf(Xb[(h * 8 + tq) * 136 + nn]);
                uint32_t b1 = f2tf(Xb[(h * 8 + tq + 4) * 136 + nn]);
#pragma unroll
                for (int mtl = 0; mtl < 4; mtl++)
                    mma_tf32(acc[mtl][ntl], a[mtl].x, a[mtl].y, a[mtl].z, a[mtl].w, b0, b1);
            }
        }
    }

    // direct epilogue: bias + residual, coalesced float2 stores
#pragma unroll
    for (int mtl = 0; mtl < 4; mtl++) {
        int row0 = wm * 64 + mtl * 16 + g;
        float bv0 = bias[row0], bv1 = bias[row0 + 8];
#pragma unroll
        for (int ntl = 0; ntl < 4; ntl++) {
            int col = s0 + wn * 32 + ntl * 8 + 2 * tq;
            size_t i0 = ((size_t)b * 128 + row0) * HW + col;
            size_t i1 = ((size_t)b * 128 + row0 + 8) * HW + col;
            float2 r0 = *(const float2*)(res + i0);
            float2 r1 = *(const float2*)(res + i1);
            *(float2*)(out + i0) = make_float2(acc[mtl][ntl][0] + bv0 + r0.x,
                                               acc[mtl][ntl][1] + bv0 + r0.y);
            *(float2*)(out + i1) = make_float2(acc[mtl][ntl][2] + bv1 + r1.x,
                                               acc[mtl][ntl][3] + bv1 + r1.y);
        }
    }
}

static const int FLASH_SMEM = 4 * 8192 * 4;          // 128 KB
static const int QKV_SMEM   = 67584 + 34816;         // Csm/Wf + 4-stage X = 102400 B
static const int POUT_SMEM  = 65536 + 34816;         // Wf + 4-stage X = 100352 B

extern "C" void kernel_launch(void* const* d_in, const int* in_sizes, int n_in,
                              void* d_out, int out_size)
{
    const float* x_upper = (const float*)d_in[0];
    const float* x_lower = (const float*)d_in[1];
    const float* wq = (const float*)d_in[2];
    const float* bq = (const float*)d_in[3];
    const float* wk = (const float*)d_in[4];
    const float* bk = (const float*)d_in[5];
    const float* wv = (const float*)d_in[6];
    const float* bv = (const float*)d_in[7];
    const float* wo = (const float*)d_in[8];
    const float* bo = (const float*)d_in[9];
    float* out = (float*)d_out;

    uint32_t *Qp, *Kp, *Vp; float* Op;
    cudaGetSymbolAddress((void**)&Qp, g_Q);
    cudaGetSymbolAddress((void**)&Kp, g_K);
    cudaGetSymbolAddress((void**)&Vp, g_V);
    cudaGetSymbolAddress((void**)&Op, g_O);

    cudaFuncSetAttribute(flash_kernel,
                         cudaFuncAttributeMaxDynamicSharedMemorySize, FLASH_SMEM);
    cudaFuncSetAttribute(proj_qkv_t,
                         cudaFuncAttributeMaxDynamicSharedMemorySize, QKV_SMEM);
    cudaFuncSetAttribute(proj_out_t,
                         cudaFuncAttributeMaxDynamicSharedMemorySize, POUT_SMEM);

    proj_qkv_t<<<dim3(32, 12), 256, QKV_SMEM>>>(x_upper, x_lower,
                                                wq, bq, wk, bk, wv, bv,
                                                Qp, Kp, Vp);

    flash_kernel<<<dim3(NTOK / 128, NB), 256, FLASH_SMEM>>>(
        (const uint4*)Qp, (const char*)Kp, (const char*)Vp, Op);

    proj_out_t<<<dim3(32, 4), 256, POUT_SMEM>>>(Op, wo, bo, x_lower, out);
}

// round 12
// speedup vs baseline: 1.3331x; 1.0861x over previous
#include <cuda_runtime.h>
#include <math.h>
#include <stdint.h>

#define NB   4
#define HW   4096
#define DH   128
#define NTOK 4096
#define QKV_U32 (NTOK * DH / 2)   // 262144 u32 (bf16x2) per batch

// Fragment images (consumed by flash, r6 layouts — unchanged):
__device__ uint32_t g_Q[NB * QKV_U32];
__device__ uint32_t g_K[NB * QKV_U32];
__device__ uint32_t g_V[NB * QKV_U32];
// Plain bf16 token rows [b][n][128] (bf16x2 per u32), written by proj, read by repack:
__device__ uint32_t g_Qp[NB * QKV_U32];
__device__ uint32_t g_Kp[NB * QKV_U32];
__device__ uint32_t g_Vp[NB * QKV_U32];
__device__ float    g_O[NB * NTOK * DH];

// log2(e)/sqrt(128): Q pre-scale so softmax runs in exp2 domain.
#define QSCALE (0.08838834764831845f * 1.4426950408889634f)

__device__ __forceinline__ uint32_t pack_bf16(float lo, float hi) {
    uint32_t r; asm("cvt.rn.bf16x2.f32 %0, %1, %2;" : "=r"(r) : "f"(hi), "f"(lo)); return r;
}
__device__ __forceinline__ float ex2f(float x) {
    float y; asm("ex2.approx.f32 %0, %1;" : "=f"(y) : "f"(x)); return y;
}
__device__ __forceinline__ uint32_t f2tf(float x) {
    uint32_t u; asm("cvt.rna.tf32.f32 %0, %1;" : "=r"(u) : "f"(x)); return u;
}
__device__ __forceinline__ void mma_tf32(float* d,
    uint32_t a0, uint32_t a1, uint32_t a2, uint32_t a3, uint32_t b0, uint32_t b1)
{
    asm volatile(
        "mma.sync.aligned.m16n8k8.row.col.f32.tf32.tf32.f32 "
        "{%0,%1,%2,%3},{%4,%5,%6,%7},{%8,%9},{%0,%1,%2,%3};"
        : "+f"(d[0]), "+f"(d[1]), "+f"(d[2]), "+f"(d[3])
        : "r"(a0), "r"(a1), "r"(a2), "r"(a3), "r"(b0), "r"(b1));
}
__device__ __forceinline__ void mma_bf16(float* d,
    uint32_t a0, uint32_t a1, uint32_t a2, uint32_t a3, uint32_t b0, uint32_t b1)
{
    asm volatile(
        "mma.sync.aligned.m16n8k16.row.col.f32.bf16.bf16.f32 "
        "{%0,%1,%2,%3},{%4,%5,%6,%7},{%8,%9},{%0,%1,%2,%3};"
        : "+f"(d[0]), "+f"(d[1]), "+f"(d[2]), "+f"(d[3])
        : "r"(a0), "r"(a1), "r"(a2), "r"(a3), "r"(b0), "r"(b1));
}
__device__ __forceinline__ void mma_bf16_init(float* d,
    uint32_t a0, uint32_t a1, uint32_t a2, uint32_t a3, uint32_t b0, uint32_t b1)
{
    asm volatile(
        "mma.sync.aligned.m16n8k16.row.col.f32.bf16.bf16.f32 "
        "{%0,%1,%2,%3},{%4,%5,%6,%7},{%8,%9},{%10,%11,%12,%13};"
        : "=f"(d[0]), "=f"(d[1]), "=f"(d[2]), "=f"(d[3])
        : "r"(a0), "r"(a1), "r"(a2), "r"(a3), "r"(b0), "r"(b1),
          "f"(0.f), "f"(0.f), "f"(0.f), "f"(0.f));
}
__device__ __forceinline__ void cp_async16(void* smem_dst, const void* gmem_src) {
    uint32_t s = (uint32_t)__cvta_generic_to_shared(smem_dst);
    asm volatile("cp.async.cg.shared.global [%0], [%1], 16;\n" :: "r"(s), "l"(gmem_src));
}
#define CP_COMMIT() asm volatile("cp.async.commit_group;\n" ::: "memory")
template<int N> __device__ __forceinline__ void cp_wait() {
    asm volatile("cp.async.wait_group %0;\n" :: "n"(N) : "memory");
}

// ---------------------------------------------------------------------------
// tf32 QKV projection (loop identical to r11). Emit: COALESCED plain bf16
// token rows — per warp one 256B contiguous burst per cc step.
// ---------------------------------------------------------------------------
__global__ __launch_bounds__(256, 2) void proj_qkv_t(
    const float* __restrict__ xu, const float* __restrict__ xl,
    const float* __restrict__ wq, const float* __restrict__ bq,
    const float* __restrict__ wk, const float* __restrict__ bk,
    const float* __restrict__ wv, const float* __restrict__ bv,
    uint32_t* __restrict__ Qp, uint32_t* __restrict__ Kp,
    uint32_t* __restrict__ Vp)
{
    extern __shared__ uint32_t shm[];
    uint32_t* Wf  = shm;                       // [mt8][KS][lane32][4] tf32 (<=64KB)
    float*    Csm = (float*)shm;               // reused: [128][132] fp32 (67584B)
    float*    Xs  = (float*)(shm + 16896);     // 4 stages x [16][136] fp32 (34816B)

    const int m = blockIdx.y % 3, b = blockIdx.y / 3;
    const int CIN = (m == 0) ? 64 : 128;
    const int KS  = CIN >> 3;
    const int NK  = CIN >> 4;
    const int CLOG = (m == 0) ? 6 : 7;
    const float* x    = (m == 0) ? xu + (size_t)b * 64 * HW
                                 : xl + (size_t)b * 128 * HW;
    const float* w    = (m == 0) ? wq : (m == 1) ? wk : wv;
    const float* bias = (m == 0) ? bq : (m == 1) ? bk : bv;

    const int s0  = blockIdx.x * 128;
    const int tid = threadIdx.x, wp = tid >> 5, lane = tid & 31;
    const int g = lane >> 2, tq = lane & 3;
    const int wm = wp >> 2, wn = wp & 3;

    auto issueX = [&](int j) {
        float* dst = Xs + (j & 3) * 2176;
#pragma unroll
        for (int tt = 0; tt < 2; tt++) {
            int f = tid + 256 * tt;
            int row = f >> 5, col = (f & 31) * 4;
            cp_async16(dst + row * 136 + col,
                       x + (size_t)(j * 16 + row) * HW + s0 + col);
        }
        CP_COMMIT();
    };
    issueX(0); issueX(1);
    if (NK > 2) issueX(2); else CP_COMMIT();

    // W -> tf32 A-frag images (overlapped with X loads)
    for (int e = tid; e < (128 << CLOG); e += 256) {
        int mrow = e >> CLOG, k = e & (CIN - 1);
        int mt = mrow >> 4, r = mrow & 15, gg = r & 7, hi = r >> 3;
        int ks = k >> 3, kk = k & 7, c = kk & 3, ch = kk >> 2;
        Wf[((mt * KS + ks) * 32 + gg * 4 + c) * 4 + hi + 2 * ch] = f2tf(w[e]);
    }

    float acc[4][4][4];
#pragma unroll
    for (int i = 0; i < 4; i++)
#pragma unroll
        for (int j = 0; j < 4; j++)
#pragma unroll
            for (int k = 0; k < 4; k++) acc[i][j][k] = 0.f;

    __syncthreads();   // Wf visible

    for (int j = 0; j < NK; j++) {
        cp_wait<2>();
        __syncthreads();
        if (j + 3 < NK) issueX(j + 3); else CP_COMMIT();
        const float* Xb = Xs + (j & 3) * 2176;

#pragma unroll
        for (int h = 0; h < 2; h++) {
            const int ks = j * 2 + h;
            uint4 a[4];
#pragma unroll
            for (int mtl = 0; mtl < 4; mtl++)
                a[mtl] = *(const uint4*)&Wf[(((wm * 4 + mtl) * KS + ks) * 32 + lane) * 4];
#pragma unroll
            for (int ntl = 0; ntl < 4; ntl++) {
                int nn = wn * 32 + ntl * 8 + g;
                uint32_t b0 = f2tf(Xb[(h * 8 + tq) * 136 + nn]);
                uint32_t b1 = f2tf(Xb[(h * 8 + tq + 4) * 136 + nn]);
#pragma unroll
                for (int mtl = 0; mtl < 4; mtl++)
                    mma_tf32(acc[mtl][ntl], a[mtl].x, a[mtl].y, a[mtl].z, a[mtl].w, b0, b1);
            }
        }
    }

    // C -> smem (aliases Wf; all A-frag reads complete)
    __syncthreads();
#pragma unroll
    for (int mtl = 0; mtl < 4; mtl++) {
        int row = wm * 64 + mtl * 16 + g;
#pragma unroll
        for (int ntl = 0; ntl < 4; ntl++) {
            int col = wn * 32 + ntl * 8 + 2 * tq;
            *(float2*)&Csm[row * 132 + col]       = make_float2(acc[mtl][ntl][0], acc[mtl][ntl][1]);
            *(float2*)&Csm[(row + 8) * 132 + col] = make_float2(acc[mtl][ntl][2], acc[mtl][ntl][3]);
        }
    }
    __syncthreads();

    // COALESCED plain emit: warp handles one token (c) per cc; lanes cover d.
    uint32_t* P = (m == 0) ? Qp : (m == 1) ? Kp : Vp;
#pragma unroll
    for (int cc = 0; cc < 16; cc++) {
        const int c  = cc * 8 + wp;           // cout row == token group
        const int sl = lane * 4;              // d0
        float4 vv4 = *(const float4*)&Csm[c * 132 + sl];
        const float bv_ = bias[c];
        float v0 = vv4.x + bv_, v1 = vv4.y + bv_;
        float v2 = vv4.z + bv_, v3 = vv4.w + bv_;
        if (m == 0) { v0 *= QSCALE; v1 *= QSCALE; v2 *= QSCALE; v3 *= QSCALE; }
        const int n = c * 32 + blockIdx.x;    // token index
        uint2 val;
        val.x = pack_bf16(v0, v1);
        val.y = pack_bf16(v2, v3);
        *(uint2*)(P + ((size_t)(b * NTOK + n)) * 64 + lane * 2) = val;
    }
}

// ---------------------------------------------------------------------------
// Repack: plain bf16 rows -> r6 fragment images. Coalesced STG.128 per lane;
// gathers via L2-resident LDG. blockIdx.y: 0=Q, 1=K, 2=V. blockIdx.z = b.
// Each warp builds one 512B chunk (32 lanes x uint4).
// ---------------------------------------------------------------------------
__global__ __launch_bounds__(256) void repack_kernel(
    const uint32_t* __restrict__ Qp, const uint32_t* __restrict__ Kp,
    const uint16_t* __restrict__ Vp,
    uint32_t* __restrict__ Qi, uint32_t* __restrict__ Ki,
    uint32_t* __restrict__ Vi)
{
    const int tid = threadIdx.x, wp = tid >> 5, lane = tid & 31;
    const int kind = blockIdx.y, b = blockIdx.z;
    const int chunk = blockIdx.x * 8 + wp;     // [0, 2048)
    const int big = chunk >> 3, ks = chunk & 7;
    const int g = lane >> 2, t = lane & 3;

    uint4 out;
    if (kind == 0) {
        // Q A-frag: u32[j'] (j' = hi + 2ch): n = big*16 + g + 8hi, du32 = ks*8 + t + 4ch
        const uint32_t* P = Qp + (size_t)b * QKV_U32;
        int r0 = (big * 16 + g) * 64 + ks * 8 + t;
        out.x = P[r0];                 // hi0 ch0
        out.y = P[r0 + 8 * 64];        // hi1 ch0
        out.z = P[r0 + 4];             // hi0 ch1
        out.w = P[r0 + 8 * 64 + 4];    // hi1 ch1
        *(uint4*)(Qi + (((size_t)b * 256 + big) * 8 + ks) * 128 + lane * 4) = out;
    } else if (kind == 1) {
        // K paired B-frag: u32[odd*2+j]: n = big*16 + 8odd + g, du32 = ks*8 + t + 4j
        const uint32_t* P = Kp + (size_t)b * QKV_U32;
        int r0 = (big * 16 + g) * 64 + ks * 8 + t;
        out.x = P[r0];                 // odd0 j0
        out.y = P[r0 + 4];             // odd0 j1
        out.z = P[r0 + 8 * 64];        // odd1 j0
        out.w = P[r0 + 8 * 64 + 4];    // odd1 j1
        *(uint4*)(Ki + (((size_t)b * 256 + big) * 8 + ks) * 128 + lane * 4) = out;
    } else {
        // V paired B-frag (k = token): u32[odd*2+j] packs tokens
        // n0 = big*16 + 8j + 2t (lo), n0+1 (hi), at d = ks*16 + 8odd + g.
        const uint16_t* P = Vp + (size_t)b * (QKV_U32 * 2);
        uint32_t r[4];
#pragma unroll
        for (int sub = 0; sub < 4; sub++) {
            int odd = sub >> 1, j = sub & 1;
            int n0 = big * 16 + 8 * j + 2 * t;
            int d  = ks * 16 + 8 * odd + g;
            uint32_t lo = P[(size_t)n0 * 128 + d];
            uint32_t hi = P[(size_t)(n0 + 1) * 128 + d];
            r[sub] = lo | (hi << 16);
        }
        out.x = r[0]; out.y = r[1]; out.z = r[2]; out.w = r[3];
        *(uint4*)(Vi + (((size_t)b * 256 + big) * 8 + ks) * 128 + lane * 4) = out;
    }
}

// ---------------------------------------------------------------------------
// bf16 flash (r6 verbatim; proven 112.7us).
// ---------------------------------------------------------------------------
__global__ __launch_bounds__(256, 1) void flash_kernel(
    const uint4* __restrict__ Qg, const char* __restrict__ Kg_,
    const char* __restrict__ Vg_, float* __restrict__ O)
{
    extern __shared__ uint32_t sm[];

    const int b = blockIdx.y, bx = blockIdx.x;
    const int tid = threadIdx.x, w = tid >> 5, lane = tid & 31;
    const int g = lane >> 2, t = lane & 3;

    const char* Kg = Kg_ + (size_t)b * (QKV_U32 * 4);
    const char* Vg = Vg_ + (size_t)b * (QKV_U32 * 4);

    auto issueKV = [&](int i) {
        uint32_t st = (uint32_t)(i & 3) * 8192;
        const char* kg = Kg + (size_t)i * 16384;
        const char* vg = Vg + (size_t)i * 16384;
#pragma unroll
        for (int tt = 0; tt < 4; tt++) {
            int f = (tid + 256 * tt) * 16;
            cp_async16((char*)(sm + st) + f, kg + f);
        }
#pragma unroll
        for (int tt = 0; tt < 4; tt++) {
            int f = (tid + 256 * tt) * 16;
            cp_async16((char*)(sm + st + 4096) + f, vg + f);
        }
        CP_COMMIT();
    };
    issueKV(0); issueKV(1); issueKV(2);

    uint4 q[8];
    {
        const uint4* qp = Qg + ((size_t)(b * 256 + bx * 8 + w) * 8) * 32 + lane;
#pragma unroll
        for (int ks = 0; ks < 8; ks++) q[ks] = qp[ks * 32];
    }

    float o[16][4];
#pragma unroll
    for (int dt = 0; dt < 16; dt++)
#pragma unroll
        for (int j = 0; j < 4; j++) o[dt][j] = 0.f;
    float ls0 = 0.f, ls1 = 0.f;
    float sf[8][4];

    cp_wait<2>();
    __syncthreads();
    {
        const uint32_t* ksb = sm;
#pragma unroll
        for (int ks = 0; ks < 8; ks++) {
#pragma unroll
            for (int ntp = 0; ntp < 4; ntp++) {
                uint4 kb = *(const uint4*)(ksb + (ntp * 8 + ks) * 128 + lane * 4);
                if (ks == 0) {
                    mma_bf16_init(sf[ntp * 2],     q[ks].x, q[ks].y, q[ks].z, q[ks].w, kb.x, kb.y);
                    mma_bf16_init(sf[ntp * 2 + 1], q[ks].x, q[ks].y, q[ks].z, q[ks].w, kb.z, kb.w);
                } else {
                    mma_bf16(sf[ntp * 2],     q[ks].x, q[ks].y, q[ks].z, q[ks].w, kb.x, kb.y);
                    mma_bf16(sf[ntp * 2 + 1], q[ks].x, q[ks].y, q[ks].z, q[ks].w, kb.z, kb.w);
                }
            }
        }
    }

    for (int i = 0; i < 64; i++) {
        cp_wait<1>();
        __syncthreads();
        if (i + 3 < 64) issueKV(i + 3); else CP_COMMIT();

        const uint32_t* ksb = sm + (uint32_t)((i + 1) & 3) * 8192;
        const uint32_t* vsb = sm + (uint32_t)(i & 3) * 8192 + 4096;

        uint32_t p[16];
#pragma unroll
        for (int u = 0; u < 4; u++) {
            float a0 = ex2f(sf[2*u][0]),   a1 = ex2f(sf[2*u][1]);
            float a2 = ex2f(sf[2*u][2]),   a3 = ex2f(sf[2*u][3]);
            float b0 = ex2f(sf[2*u+1][0]), b1 = ex2f(sf[2*u+1][1]);
            float b2 = ex2f(sf[2*u+1][2]), b3 = ex2f(sf[2*u+1][3]);
            ls0 += a0 + a1 + b0 + b1;
            ls1 += a2 + a3 + b2 + b3;
            p[u*4+0] = pack_bf16(a0, a1);
            p[u*4+1] = pack_bf16(a2, a3);
            p[u*4+2] = pack_bf16(b0, b1);
            p[u*4+3] = pack_bf16(b2, b3);
        }

        if (i < 63) {
#pragma unroll
            for (int ks = 0; ks < 8; ks++) {
#pragma unroll
                for (int ntp = 0; ntp < 4; ntp++) {
                    uint4 kb = *(const uint4*)(ksb + (ntp * 8 + ks) * 128 + lane * 4);
                    if (ks == 0) {
                        mma_bf16_init(sf[ntp * 2],     q[ks].x, q[ks].y, q[ks].z, q[ks].w, kb.x, kb.y);
                        mma_bf16_init(sf[ntp * 2 + 1], q[ks].x, q[ks].y, q[ks].z, q[ks].w, kb.z, kb.w);
                    } else {
                        mma_bf16(sf[ntp * 2],     q[ks].x, q[ks].y, q[ks].z, q[ks].w, kb.x, kb.y);
                        mma_bf16(sf[ntp * 2 + 1], q[ks].x, q[ks].y, q[ks].z, q[ks].w, kb.z, kb.w);
                    }
                }
            }
        }

#pragma unroll
        for (int u = 0; u < 4; u++) {
#pragma unroll
            for (int dtp = 0; dtp < 8; dtp++) {
                uint4 vv = *(const uint4*)(vsb + (u * 8 + dtp) * 128 + lane * 4);
                mma_bf16(o[dtp * 2],     p[u*4+0], p[u*4+1], p[u*4+2], p[u*4+3], vv.x, vv.y);
                mma_bf16(o[dtp * 2 + 1], p[u*4+0], p[u*4+1], p[u*4+2], p[u*4+3], vv.z, vv.w);
            }
        }
    }

    ls0 += __shfl_xor_sync(0xffffffffu, ls0, 1);
    ls0 += __shfl_xor_sync(0xffffffffu, ls0, 2);
    ls1 += __shfl_xor_sync(0xffffffffu, ls1, 1);
    ls1 += __shfl_xor_sync(0xffffffffu, ls1, 2);
    const float inv0 = 1.0f / ls0, inv1 = 1.0f / ls1;

    float* Ob = O + ((size_t)(b * NTOK) + bx * 128 + w * 16) * DH;
#pragma unroll
    for (int dt = 0; dt < 16; dt++) {
        *(float2*)(Ob + g * DH + dt * 8 + 2 * t) =
            make_float2(o[dt][0] * inv0, o[dt][1] * inv0);
        *(float2*)(Ob + (g + 8) * DH + dt * 8 + 2 * t) =
            make_float2(o[dt][2] * inv1, o[dt][3] * inv1);
    }
}

// ---------------------------------------------------------------------------
// tf32 final conv (r11 verbatim). out = wo @ O + bo + x_lower.
// ---------------------------------------------------------------------------
__global__ __launch_bounds__(256, 2) void proj_out_t(
    const float* __restrict__ Oin, const float* __restrict__ w,
    const float* __restrict__ bias, const float* __restrict__ res,
    float* __restrict__ out)
{
    extern __shared__ uint32_t shm[];
    uint32_t* Wf = shm;
    float*    Xs = (float*)(shm + 16384);

    const int b  = blockIdx.y;
    const int s0 = blockIdx.x * 128;
    const int tid = threadIdx.x, wp = tid >> 5, lane = tid & 31;
    const int g = lane >> 2, tq = lane & 3;
    const int wm = wp >> 2, wn = wp & 3;

    const float* x = Oin + (size_t)b * 128 * HW;

    auto issueX = [&](int j) {
        float* dst = Xs + (j & 3) * 2176;
#pragma unroll
        for (int tt = 0; tt < 2; tt++) {
            int f = tid + 256 * tt;
            int row = f >> 5, col = (f & 31) * 4;
            cp_async16(dst + row * 136 + col,
                       x + (size_t)(j * 16 + row) * HW + s0 + col);
        }
        CP_COMMIT();
    };
    issueX(0); issueX(1); issueX(2);

    for (int e = tid; e < 128 * 128; e += 256) {
        int mrow = e >> 7, k = e & 127;
        int mt = mrow >> 4, r = mrow & 15, gg = r & 7, hi = r >> 3;
        int ks = k >> 3, kk = k & 7, c = kk & 3, ch = kk >> 2;
        Wf[((mt * 16 + ks) * 32 + gg * 4 + c) * 4 + hi + 2 * ch] = f2tf(w[e]);
    }

    float acc[4][4][4];
#pragma unroll
    for (int i = 0; i < 4; i++)
#pragma unroll
        for (int j = 0; j < 4; j++)
#pragma unroll
            for (int k = 0; k < 4; k++) acc[i][j][k] = 0.f;

    __syncthreads();

    for (int j = 0; j < 8; j++) {
        cp_wait<2>();
        __syncthreads();
        if (j + 3 < 8) issueX(j + 3); else CP_COMMIT();
        const float* Xb = Xs + (j & 3) * 2176;

#pragma unroll
        for (int h = 0; h < 2; h++) {
            const int ks = j * 2 + h;
            uint4 a[4];
#pragma unroll
            for (int mtl = 0; mtl < 4; mtl++)
                a[mtl] = *(const uint4*)&Wf[(((wm * 4 + mtl) * 16 + ks) * 32 + lane) * 4];
#pragma unroll
            for (int ntl = 0; ntl < 4; ntl++) {
                int nn = wn * 32 + ntl * 8 + g;
                uint32_t b0 = f2tf(Xb[(h * 8 + tq) * 136 + nn]);
                uint32_t b1 = f2tf(Xb[(h * 8 + tq + 4) * 136 + nn]);
#pragma unroll
                for (int mtl = 0; mtl < 4; mtl++)
                    mma_tf32(acc[mtl][ntl], a[mtl].x, a[mtl].y, a[mtl].z, a[mtl].w, b0, b1);
            }
        }
    }

#pragma unroll
    for (int mtl = 0; mtl < 4; mtl++) {
        int row0 = wm * 64 + mtl * 16 + g;
        float bv0 = bias[row0], bv1 = bias[row0 + 8];
#pragma unroll
        for (int ntl = 0; ntl < 4; ntl++) {
            int col = s0 + wn * 32 + ntl * 8 + 2 * tq;
            size_t i0 = ((size_t)b * 128 + row0) * HW + col;
            size_t i1 = ((size_t)b * 128 + row0 + 8) * HW + col;
            float2 r0 = *(const float2*)(res + i0);
            float2 r1 = *(const float2*)(res + i1);
            *(float2*)(out + i0) = make_float2(acc[mtl][ntl][0] + bv0 + r0.x,
                                               acc[mtl][ntl][1] + bv0 + r0.y);
            *(float2*)(out + i1) = make_float2(acc[mtl][ntl][2] + bv1 + r1.x,
                                               acc[mtl][ntl][3] + bv1 + r1.y);
        }
    }
}

static const int FLASH_SMEM = 4 * 8192 * 4;          // 128 KB
static const int QKV_SMEM   = 67584 + 34816;         // 102400 B
static const int POUT_SMEM  = 65536 + 34816;         // 100352 B

extern "C" void kernel_launch(void* const* d_in, const int* in_sizes, int n_in,
                              void* d_out, int out_size)
{
    const float* x_upper = (const float*)d_in[0];
    const float* x_lower = (const float*)d_in[1];
    const float* wq = (const float*)d_in[2];
    const float* bq = (const float*)d_in[3];
    const float* wk = (const float*)d_in[4];
    const float* bk = (const float*)d_in[5];
    const float* wv = (const float*)d_in[6];
    const float* bv = (const float*)d_in[7];
    const float* wo = (const float*)d_in[8];
    const float* bo = (const float*)d_in[9];
    float* out = (float*)d_out;

    uint32_t *Qi, *Ki, *Vi, *Qp, *Kp, *Vp; float* Op;
    cudaGetSymbolAddress((void**)&Qi, g_Q);
    cudaGetSymbolAddress((void**)&Ki, g_K);
    cudaGetSymbolAddress((void**)&Vi, g_V);
    cudaGetSymbolAddress((void**)&Qp, g_Qp);
    cudaGetSymbolAddress((void**)&Kp, g_Kp);
    cudaGetSymbolAddress((void**)&Vp, g_Vp);
    cudaGetSymbolAddress((void**)&Op, g_O);

    cudaFuncSetAttribute(flash_kernel,
                         cudaFuncAttributeMaxDynamicSharedMemorySize, FLASH_SMEM);
    cudaFuncSetAttribute(proj_qkv_t,
                         cudaFuncAttributeMaxDynamicSharedMemorySize, QKV_SMEM);
    cudaFuncSetAttribute(proj_out_t,
                         cudaFuncAttributeMaxDynamicSharedMemorySize, POUT_SMEM);

    proj_qkv_t<<<dim3(32, 12), 256, QKV_SMEM>>>(x_upper, x_lower,
                                                wq, bq, wk, bk, wv, bv,
                                                Qp, Kp, Vp);

    repack_kernel<<<dim3(256, 3, NB), 256>>>(Qp, Kp, (const uint16_t*)Vp,
                                             Qi, Ki, Vi);

    flash_kernel<<<dim3(NTOK / 128, NB), 256, FLASH_SMEM>>>(
        (const uint4*)Qi, (const char*)Ki, (const char*)Vi, Op);

    proj_out_t<<<dim3(32, 4), 256, POUT_SMEM>>>(Op, wo, bo, x_lower, out);
}

// round 13
// speedup vs baseline: 1.3765x; 1.0326x over previous
#include <cuda_runtime.h>
#include <math.h>
#include <stdint.h>

#define NB   4
#define HW   4096
#define DH   128
#define NTOK 4096
#define QKV_U32 (NTOK * DH / 2)   // 262144 u32 (bf16x2) per batch

// Fragment images (consumed by flash, r6 layouts):
__device__ uint32_t g_Q[NB * QKV_U32];
__device__ uint32_t g_K[NB * QKV_U32];
__device__ uint32_t g_V[NB * QKV_U32];
// Plain bf16 token rows [b][n][128], written by proj, read by repack:
__device__ uint32_t g_Qp[NB * QKV_U32];
__device__ uint32_t g_Kp[NB * QKV_U32];
__device__ uint32_t g_Vp[NB * QKV_U32];
__device__ float    g_O[NB * NTOK * DH];

// log2(e)/sqrt(128): Q pre-scale so softmax runs in exp2 domain.
#define QSCALE (0.08838834764831845f * 1.4426950408889634f)

__device__ __forceinline__ uint32_t pack_bf16(float lo, float hi) {
    uint32_t r; asm("cvt.rn.bf16x2.f32 %0, %1, %2;" : "=r"(r) : "f"(hi), "f"(lo)); return r;
}
__device__ __forceinline__ float ex2f(float x) {
    float y; asm("ex2.approx.f32 %0, %1;" : "=f"(y) : "f"(x)); return y;
}
__device__ __forceinline__ uint32_t f2tf(float x) {
    uint32_t u; asm("cvt.rna.tf32.f32 %0, %1;" : "=r"(u) : "f"(x)); return u;
}
__device__ __forceinline__ void mma_tf32(float* d,
    uint32_t a0, uint32_t a1, uint32_t a2, uint32_t a3, uint32_t b0, uint32_t b1)
{
    asm volatile(
        "mma.sync.aligned.m16n8k8.row.col.f32.tf32.tf32.f32 "
        "{%0,%1,%2,%3},{%4,%5,%6,%7},{%8,%9},{%0,%1,%2,%3};"
        : "+f"(d[0]), "+f"(d[1]), "+f"(d[2]), "+f"(d[3])
        : "r"(a0), "r"(a1), "r"(a2), "r"(a3), "r"(b0), "r"(b1));
}
__device__ __forceinline__ void mma_bf16(float* d,
    uint32_t a0, uint32_t a1, uint32_t a2, uint32_t a3, uint32_t b0, uint32_t b1)
{
    asm volatile(
        "mma.sync.aligned.m16n8k16.row.col.f32.bf16.bf16.f32 "
        "{%0,%1,%2,%3},{%4,%5,%6,%7},{%8,%9},{%0,%1,%2,%3};"
        : "+f"(d[0]), "+f"(d[1]), "+f"(d[2]), "+f"(d[3])
        : "r"(a0), "r"(a1), "r"(a2), "r"(a3), "r"(b0), "r"(b1));
}
__device__ __forceinline__ void mma_bf16_init(float* d,
    uint32_t a0, uint32_t a1, uint32_t a2, uint32_t a3, uint32_t b0, uint32_t b1)
{
    asm volatile(
        "mma.sync.aligned.m16n8k16.row.col.f32.bf16.bf16.f32 "
        "{%0,%1,%2,%3},{%4,%5,%6,%7},{%8,%9},{%10,%11,%12,%13};"
        : "=f"(d[0]), "=f"(d[1]), "=f"(d[2]), "=f"(d[3])
        : "r"(a0), "r"(a1), "r"(a2), "r"(a3), "r"(b0), "r"(b1),
          "f"(0.f), "f"(0.f), "f"(0.f), "f"(0.f));
}
__device__ __forceinline__ void cp_async16(void* smem_dst, const void* gmem_src) {
    uint32_t s = (uint32_t)__cvta_generic_to_shared(smem_dst);
    asm volatile("cp.async.cg.shared.global [%0], [%1], 16;\n" :: "r"(s), "l"(gmem_src));
}
#define CP_COMMIT() asm volatile("cp.async.commit_group;\n" ::: "memory")
template<int N> __device__ __forceinline__ void cp_wait() {
    asm volatile("cp.async.wait_group %0;\n" :: "n"(N) : "memory");
}

// ---------------------------------------------------------------------------
// tf32 QKV projection (r12 verbatim): coalesced plain bf16 token-row emit.
// ---------------------------------------------------------------------------
__global__ __launch_bounds__(256, 2) void proj_qkv_t(
    const float* __restrict__ xu, const float* __restrict__ xl,
    const float* __restrict__ wq, const float* __restrict__ bq,
    const float* __restrict__ wk, const float* __restrict__ bk,
    const float* __restrict__ wv, const float* __restrict__ bv,
    uint32_t* __restrict__ Qp, uint32_t* __restrict__ Kp,
    uint32_t* __restrict__ Vp)
{
    extern __shared__ uint32_t shm[];
    uint32_t* Wf  = shm;
    float*    Csm = (float*)shm;
    float*    Xs  = (float*)(shm + 16896);

    const int m = blockIdx.y % 3, b = blockIdx.y / 3;
    const int CIN = (m == 0) ? 64 : 128;
    const int KS  = CIN >> 3;
    const int NK  = CIN >> 4;
    const int CLOG = (m == 0) ? 6 : 7;
    const float* x    = (m == 0) ? xu + (size_t)b * 64 * HW
                                 : xl + (size_t)b * 128 * HW;
    const float* w    = (m == 0) ? wq : (m == 1) ? wk : wv;
    const float* bias = (m == 0) ? bq : (m == 1) ? bk : bv;

    const int s0  = blockIdx.x * 128;
    const int tid = threadIdx.x, wp = tid >> 5, lane = tid & 31;
    const int g = lane >> 2, tq = lane & 3;
    const int wm = wp >> 2, wn = wp & 3;

    auto issueX = [&](int j) {
        float* dst = Xs + (j & 3) * 2176;
#pragma unroll
        for (int tt = 0; tt < 2; tt++) {
            int f = tid + 256 * tt;
            int row = f >> 5, col = (f & 31) * 4;
            cp_async16(dst + row * 136 + col,
                       x + (size_t)(j * 16 + row) * HW + s0 + col);
        }
        CP_COMMIT();
    };
    issueX(0); issueX(1);
    if (NK > 2) issueX(2); else CP_COMMIT();

    for (int e = tid; e < (128 << CLOG); e += 256) {
        int mrow = e >> CLOG, k = e & (CIN - 1);
        int mt = mrow >> 4, r = mrow & 15, gg = r & 7, hi = r >> 3;
        int ks = k >> 3, kk = k & 7, c = kk & 3, ch = kk >> 2;
        Wf[((mt * KS + ks) * 32 + gg * 4 + c) * 4 + hi + 2 * ch] = f2tf(w[e]);
    }

    float acc[4][4][4];
#pragma unroll
    for (int i = 0; i < 4; i++)
#pragma unroll
        for (int j = 0; j < 4; j++)
#pragma unroll
            for (int k = 0; k < 4; k++) acc[i][j][k] = 0.f;

    __syncthreads();

    for (int j = 0; j < NK; j++) {
        cp_wait<2>();
        __syncthreads();
        if (j + 3 < NK) issueX(j + 3); else CP_COMMIT();
        const float* Xb = Xs + (j & 3) * 2176;

#pragma unroll
        for (int h = 0; h < 2; h++) {
            const int ks = j * 2 + h;
            uint4 a[4];
#pragma unroll
            for (int mtl = 0; mtl < 4; mtl++)
                a[mtl] = *(const uint4*)&Wf[(((wm * 4 + mtl) * KS + ks) * 32 + lane) * 4];
#pragma unroll
            for (int ntl = 0; ntl < 4; ntl++) {
                int nn = wn * 32 + ntl * 8 + g;
                uint32_t b0 = f2tf(Xb[(h * 8 + tq) * 136 + nn]);
                uint32_t b1 = f2tf(Xb[(h * 8 + tq + 4) * 136 + nn]);
#pragma unroll
                for (int mtl = 0; mtl < 4; mtl++)
                    mma_tf32(acc[mtl][ntl], a[mtl].x, a[mtl].y, a[mtl].z, a[mtl].w, b0, b1);
            }
        }
    }

    __syncthreads();
#pragma unroll
    for (int mtl = 0; mtl < 4; mtl++) {
        int row = wm * 64 + mtl * 16 + g;
#pragma unroll
        for (int ntl = 0; ntl < 4; ntl++) {
            int col = wn * 32 + ntl * 8 + 2 * tq;
            *(float2*)&Csm[row * 132 + col]       = make_float2(acc[mtl][ntl][0], acc[mtl][ntl][1]);
            *(float2*)&Csm[(row + 8) * 132 + col] = make_float2(acc[mtl][ntl][2], acc[mtl][ntl][3]);
        }
    }
    __syncthreads();

    uint32_t* P = (m == 0) ? Qp : (m == 1) ? Kp : Vp;
#pragma unroll
    for (int cc = 0; cc < 16; cc++) {
        const int c  = cc * 8 + wp;
        const int sl = lane * 4;
        float4 vv4 = *(const float4*)&Csm[c * 132 + sl];
        const float bv_ = bias[c];
        float v0 = vv4.x + bv_, v1 = vv4.y + bv_;
        float v2 = vv4.z + bv_, v3 = vv4.w + bv_;
        if (m == 0) { v0 *= QSCALE; v1 *= QSCALE; v2 *= QSCALE; v3 *= QSCALE; }
        const int n = c * 32 + blockIdx.x;
        uint2 val;
        val.x = pack_bf16(v0, v1);
        val.y = pack_bf16(v2, v3);
        *(uint2*)(P + ((size_t)(b * NTOK + n)) * 64 + lane * 2) = val;
    }
}

// ---------------------------------------------------------------------------
// Repack (r12 verbatim): plain rows -> fragment images, coalesced STG.128.
// ---------------------------------------------------------------------------
__global__ __launch_bounds__(256) void repack_kernel(
    const uint32_t* __restrict__ Qp, const uint32_t* __restrict__ Kp,
    const uint16_t* __restrict__ Vp,
    uint32_t* __restrict__ Qi, uint32_t* __restrict__ Ki,
    uint32_t* __restrict__ Vi)
{
    const int tid = threadIdx.x, wp = tid >> 5, lane = tid & 31;
    const int kind = blockIdx.y, b = blockIdx.z;
    const int chunk = blockIdx.x * 8 + wp;
    const int big = chunk >> 3, ks = chunk & 7;
    const int g = lane >> 2, t = lane & 3;

    uint4 out;
    if (kind == 0) {
        const uint32_t* P = Qp + (size_t)b * QKV_U32;
        int r0 = (big * 16 + g) * 64 + ks * 8 + t;
        out.x = P[r0];
        out.y = P[r0 + 8 * 64];
        out.z = P[r0 + 4];
        out.w = P[r0 + 8 * 64 + 4];
        *(uint4*)(Qi + (((size_t)b * 256 + big) * 8 + ks) * 128 + lane * 4) = out;
    } else if (kind == 1) {
        const uint32_t* P = Kp + (size_t)b * QKV_U32;
        int r0 = (big * 16 + g) * 64 + ks * 8 + t;
        out.x = P[r0];
        out.y = P[r0 + 4];
        out.z = P[r0 + 8 * 64];
        out.w = P[r0 + 8 * 64 + 4];
        *(uint4*)(Ki + (((size_t)b * 256 + big) * 8 + ks) * 128 + lane * 4) = out;
    } else {
        const uint16_t* P = Vp + (size_t)b * (QKV_U32 * 2);
        uint32_t r[4];
#pragma unroll
        for (int sub = 0; sub < 4; sub++) {
            int odd = sub >> 1, j = sub & 1;
            int n0 = big * 16 + 8 * j + 2 * t;
            int d  = ks * 16 + 8 * odd + g;
            uint32_t lo = P[(size_t)n0 * 128 + d];
            uint32_t hi = P[(size_t)(n0 + 1) * 128 + d];
            r[sub] = lo | (hi << 16);
        }
        out.x = r[0]; out.y = r[1]; out.z = r[2]; out.w = r[3];
        *(uint4*)(Vi + (((size_t)b * 256 + big) * 8 + ks) * 128 + lane * 4) = out;
    }
}

// ---------------------------------------------------------------------------
// bf16 flash with SPLIT-GROUP pipelines: warps 0-3 (group 0) and 4-7 (group 1)
// each own a 3-stage K/V smem pipeline + named barrier; no inter-group syncs.
// Each SMSP hosts one warp of each group -> softmax of one overlaps MMAs of
// the other. Math identical to r6.
// ---------------------------------------------------------------------------
__global__ __launch_bounds__(256, 1) void flash_kernel(
    const uint4* __restrict__ Qg, const char* __restrict__ Kg_,
    const char* __restrict__ Vg_, float* __restrict__ O)
{
    extern __shared__ uint32_t sm[];   // group grp at sm + grp*24576: 3 stages x (K 4096 + V 4096)

    const int b = blockIdx.y, bx = blockIdx.x;
    const int tid = threadIdx.x, w = tid >> 5, lane = tid & 31;
    const int g = lane >> 2, t = lane & 3;
    const int grp = w >> 2;
    const int gtid = tid & 127;
    uint32_t* gb = sm + grp * 24576;

    const char* Kg = Kg_ + (size_t)b * (QKV_U32 * 4);
    const char* Vg = Vg_ + (size_t)b * (QKV_U32 * 4);

    auto barG = [&]() {
        asm volatile("bar.sync %0, %1;" :: "r"(grp + 1), "r"(128) : "memory");
    };

    auto issueKV = [&](int i) {
        uint32_t* st = gb + (i % 3) * 8192;
        const char* kg = Kg + (size_t)i * 16384;
        const char* vg = Vg + (size_t)i * 16384;
#pragma unroll
        for (int tt = 0; tt < 8; tt++) {
            int f = (gtid + 128 * tt) * 16;
            cp_async16((char*)st + f, kg + f);
        }
#pragma unroll
        for (int tt = 0; tt < 8; tt++) {
            int f = (gtid + 128 * tt) * 16;
            cp_async16((char*)(st + 4096) + f, vg + f);
        }
        CP_COMMIT();
    };
    issueKV(0); issueKV(1); issueKV(2);

    uint4 q[8];
    {
        const uint4* qp = Qg + ((size_t)(b * 256 + bx * 8 + w) * 8) * 32 + lane;
#pragma unroll
        for (int ks = 0; ks < 8; ks++) q[ks] = qp[ks * 32];
    }

    float o[16][4];
#pragma unroll
    for (int dt = 0; dt < 16; dt++)
#pragma unroll
        for (int j = 0; j < 4; j++) o[dt][j] = 0.f;
    float ls0 = 0.f, ls1 = 0.f;
    float sf[8][4];

    cp_wait<2>();
    barG();
    {
        const uint32_t* ksb = gb;
#pragma unroll
        for (int ks = 0; ks < 8; ks++) {
#pragma unroll
            for (int ntp = 0; ntp < 4; ntp++) {
                uint4 kb = *(const uint4*)(ksb + (ntp * 8 + ks) * 128 + lane * 4);
                if (ks == 0) {
                    mma_bf16_init(sf[ntp * 2],     q[ks].x, q[ks].y, q[ks].z, q[ks].w, kb.x, kb.y);
                    mma_bf16_init(sf[ntp * 2 + 1], q[ks].x, q[ks].y, q[ks].z, q[ks].w, kb.z, kb.w);
                } else {
                    mma_bf16(sf[ntp * 2],     q[ks].x, q[ks].y, q[ks].z, q[ks].w, kb.x, kb.y);
                    mma_bf16(sf[ntp * 2 + 1], q[ks].x, q[ks].y, q[ks].z, q[ks].w, kb.z, kb.w);
                }
            }
        }
    }

    for (int i = 0; i < 64; i++) {
        cp_wait<1>();          // this thread's groups <= i+1 complete
        barG();                // whole group past it -> stages i, i+1 visible

        const uint32_t* ksb = gb + ((i + 1) % 3) * 8192;
        const uint32_t* vsb = gb + (i % 3) * 8192 + 4096;

        uint32_t p[16];
#pragma unroll
        for (int u = 0; u < 4; u++) {
            float a0 = ex2f(sf[2*u][0]),   a1 = ex2f(sf[2*u][1]);
            float a2 = ex2f(sf[2*u][2]),   a3 = ex2f(sf[2*u][3]);
            float b0 = ex2f(sf[2*u+1][0]), b1 = ex2f(sf[2*u+1][1]);
            float b2 = ex2f(sf[2*u+1][2]), b3 = ex2f(sf[2*u+1][3]);
            ls0 += a0 + a1 + b0 + b1;
            ls1 += a2 + a3 + b2 + b3;
            p[u*4+0] = pack_bf16(a0, a1);
            p[u*4+1] = pack_bf16(a2, a3);
            p[u*4+2] = pack_bf16(b0, b1);
            p[u*4+3] = pack_bf16(b2, b3);
        }

        if (i < 63) {
#pragma unroll
            for (int ks = 0; ks < 8; ks++) {
#pragma unroll
                for (int ntp = 0; ntp < 4; ntp++) {
                    uint4 kb = *(const uint4*)(ksb + (ntp * 8 + ks) * 128 + lane * 4);
                    if (ks == 0) {
                        mma_bf16_init(sf[ntp * 2],     q[ks].x, q[ks].y, q[ks].z, q[ks].w, kb.x, kb.y);
                        mma_bf16_init(sf[ntp * 2 + 1], q[ks].x, q[ks].y, q[ks].z, q[ks].w, kb.z, kb.w);
                    } else {
                        mma_bf16(sf[ntp * 2],     q[ks].x, q[ks].y, q[ks].z, q[ks].w, kb.x, kb.y);
                        mma_bf16(sf[ntp * 2 + 1], q[ks].x, q[ks].y, q[ks].z, q[ks].w, kb.z, kb.w);
                    }
                }
            }
        }

#pragma unroll
        for (int u = 0; u < 4; u++) {
#pragma unroll
            for (int dtp = 0; dtp < 8; dtp++) {
                uint4 vv = *(const uint4*)(vsb + (u * 8 + dtp) * 128 + lane * 4);
                mma_bf16(o[dtp * 2],     p[u*4+0], p[u*4+1], p[u*4+2], p[u*4+3], vv.x, vv.y);
                mma_bf16(o[dtp * 2 + 1], p[u*4+0], p[u*4+1], p[u*4+2], p[u*4+3], vv.z, vv.w);
            }
        }

        barG();                // group done reading stage i%3
        if (i + 3 < 64) issueKV(i + 3);   // overwrites stage (i+3)%3 == i%3
        else            CP_COMMIT();
    }

    ls0 += __shfl_xor_sync(0xffffffffu, ls0, 1);
    ls0 += __shfl_xor_sync(0xffffffffu, ls0, 2);
    ls1 += __shfl_xor_sync(0xffffffffu, ls1, 1);
    ls1 += __shfl_xor_sync(0xffffffffu, ls1, 2);
    const float inv0 = 1.0f / ls0, inv1 = 1.0f / ls1;

    float* Ob = O + ((size_t)(b * NTOK) + bx * 128 + w * 16) * DH;
#pragma unroll
    for (int dt = 0; dt < 16; dt++) {
        *(float2*)(Ob + g * DH + dt * 8 + 2 * t) =
            make_float2(o[dt][0] * inv0, o[dt][1] * inv0);
        *(float2*)(Ob + (g + 8) * DH + dt * 8 + 2 * t) =
            make_float2(o[dt][2] * inv1, o[dt][3] * inv1);
    }
}

// ---------------------------------------------------------------------------
// tf32 final conv, 64-cout tiles (grid x=spatial, y=batch, z=cout half):
// smem 67.6 KB -> 3 CTAs/SM. out = wo @ O + bo + x_lower.
// ---------------------------------------------------------------------------
__global__ __launch_bounds__(256, 3) void proj_out_t(
    const float* __restrict__ Oin, const float* __restrict__ w,
    const float* __restrict__ bias, const float* __restrict__ res,
    float* __restrict__ out)
{
    extern __shared__ uint32_t shm[];
    uint32_t* Wf = shm;                       // [mt4][16][lane32][4] tf32 (32KB)
    float*    Xs = (float*)(shm + 8192);      // 4 stages x [16][136] fp32

    const int b  = blockIdx.y;
    const int s0 = blockIdx.x * 128;
    const int crow0 = blockIdx.z * 64;
    const int tid = threadIdx.x, wp = tid >> 5, lane = tid & 31;
    const int g = lane >> 2, tq = lane & 3;
    const int wm = wp >> 2, wn = wp & 3;

    const float* x = Oin + (size_t)b * 128 * HW;

    auto issueX = [&](int j) {
        float* dst = Xs + (j & 3) * 2176;
#pragma unroll
        for (int tt = 0; tt < 2; tt++) {
            int f = tid + 256 * tt;
            int row = f >> 5, col = (f & 31) * 4;
            cp_async16(dst + row * 136 + col,
                       x + (size_t)(j * 16 + row) * HW + s0 + col);
        }
        CP_COMMIT();
    };
    issueX(0); issueX(1); issueX(2);

    // W rows [crow0, crow0+64) -> tf32 A-frag images
    for (int e = tid; e < 64 * 128; e += 256) {
        int mrow = e >> 7, k = e & 127;
        int mt = mrow >> 4, r = mrow & 15, gg = r & 7, hi = r >> 3;
        int ks = k >> 3, kk = k & 7, c = kk & 3, ch = kk >> 2;
        Wf[((mt * 16 + ks) * 32 + gg * 4 + c) * 4 + hi + 2 * ch] =
            f2tf(w[(size_t)(crow0 + mrow) * 128 + k]);
    }

    float acc[2][4][4];
#pragma unroll
    for (int i = 0; i < 2; i++)
#pragma unroll
        for (int j = 0; j < 4; j++)
#pragma unroll
            for (int k = 0; k < 4; k++) acc[i][j][k] = 0.f;

    __syncthreads();

    for (int j = 0; j < 8; j++) {
        cp_wait<2>();
        __syncthreads();
        if (j + 3 < 8) issueX(j + 3); else CP_COMMIT();
        const float* Xb = Xs + (j & 3) * 2176;

#pragma unroll
        for (int h = 0; h < 2; h++) {
            const int ks = j * 2 + h;
            uint4 a[2];
#pragma unroll
            for (int mtl = 0; mtl < 2; mtl++)
                a[mtl] = *(const uint4*)&Wf[(((wm * 2 + mtl) * 16 + ks) * 32 + lane) * 4];
#pragma unroll
            for (int ntl = 0; ntl < 4; ntl++) {
                int nn = wn * 32 + ntl * 8 + g;
                uint32_t b0 = f2tf(Xb[(h * 8 + tq) * 136 + nn]);
                uint32_t b1 = f2tf(Xb[(h * 8 + tq + 4) * 136 + nn]);
#pragma unroll
                for (int mtl = 0; mtl < 2; mtl++)
                    mma_tf32(acc[mtl][ntl], a[mtl].x, a[mtl].y, a[mtl].z, a[mtl].w, b0, b1);
            }
        }
    }

#pragma unroll
    for (int mtl = 0; mtl < 2; mtl++) {
        int row0 = crow0 + wm * 32 + mtl * 16 + g;
        float bv0 = bias[row0], bv1 = bias[row0 + 8];
#pragma unroll
        for (int ntl = 0; ntl < 4; ntl++) {
            int col = s0 + wn * 32 + ntl * 8 + 2 * tq;
            size_t i0 = ((size_t)b * 128 + row0) * HW + col;
            size_t i1 = ((size_t)b * 128 + row0 + 8) * HW + col;
            float2 r0 = *(const float2*)(res + i0);
            float2 r1 = *(const float2*)(res + i1);
            *(float2*)(out + i0) = make_float2(acc[mtl][ntl][0] + bv0 + r0.x,
                                               acc[mtl][ntl][1] + bv0 + r0.y);
            *(float2*)(out + i1) = make_float2(acc[mtl][ntl][2] + bv1 + r1.x,
                                               acc[mtl][ntl][3] + bv1 + r1.y);
        }
    }
}

static const int FLASH_SMEM = 2 * 3 * 8192 * 4;      // 192 KB (2 groups x 3 stages)
static const int QKV_SMEM   = 67584 + 34816;         // 102400 B
static const int POUT_SMEM  = 32768 + 34816;         // 67584 B

extern "C" void kernel_launch(void* const* d_in, const int* in_sizes, int n_in,
                              void* d_out, int out_size)
{
    const float* x_upper = (const float*)d_in[0];
    const float* x_lower = (const float*)d_in[1];
    const float* wq = (const float*)d_in[2];
    const float* bq = (const float*)d_in[3];
    const float* wk = (const float*)d_in[4];
    const float* bk = (const float*)d_in[5];
    const float* wv = (const float*)d_in[6];
    const float* bv = (const float*)d_in[7];
    const float* wo = (const float*)d_in[8];
    const float* bo = (const float*)d_in[9];
    float* out = (float*)d_out;

    uint32_t *Qi, *Ki, *Vi, *Qp, *Kp, *Vp; float* Op;
    cudaGetSymbolAddress((void**)&Qi, g_Q);
    cudaGetSymbolAddress((void**)&Ki, g_K);
    cudaGetSymbolAddress((void**)&Vi, g_V);
    cudaGetSymbolAddress((void**)&Qp, g_Qp);
    cudaGetSymbolAddress((void**)&Kp, g_Kp);
    cudaGetSymbolAddress((void**)&Vp, g_Vp);
    cudaGetSymbolAddress((void**)&Op, g_O);

    cudaFuncSetAttribute(flash_kernel,
                         cudaFuncAttributeMaxDynamicSharedMemorySize, FLASH_SMEM);
    cudaFuncSetAttribute(proj_qkv_t,
                         cudaFuncAttributeMaxDynamicSharedMemorySize, QKV_SMEM);
    cudaFuncSetAttribute(proj_out_t,
                         cudaFuncAttributeMaxDynamicSharedMemorySize, POUT_SMEM);

    proj_qkv_t<<<dim3(32, 12), 256, QKV_SMEM>>>(x_upper, x_lower,
                                                wq, bq, wk, bk, wv, bv,
                                                Qp, Kp, Vp);

    repack_kernel<<<dim3(256, 3, NB), 256>>>(Qp, Kp, (const uint16_t*)Vp,
                                             Qi, Ki, Vi);

    flash_kernel<<<dim3(NTOK / 128, NB), 256, FLASH_SMEM>>>(
        (const uint4*)Qi, (const char*)Ki, (const char*)Vi, Op);

    proj_out_t<<<dim3(32, 4, 2), 256, POUT_SMEM>>>(Op, wo, bo, x_lower, out);
}